// round 6
// baseline (speedup 1.0000x reference)
#include <cuda_runtime.h>
#include <math.h>

#define LNUM 4
#define DDIM 512
#define HDIM 512
#define BSZ  32
#define TSTEPS 2048
#define EPS 1e-5f
#define NCTA 128   // persistent CTAs: 4 layers x 32 row-blocks of 16 rows

// ---------------- device scratch (sanctioned: __device__ globals) ------------
__device__ float    g_A[(size_t)LNUM * TSTEPS * HDIM * BSZ];   // LN(zi): [l][t][h][b]
__device__ float    g_H3[(size_t)TSTEPS * HDIM * BSZ];         // layer-3 h: [t][h][b]
__device__ float    g_h[2 * LNUM * HDIM * BSZ];                // dbl-buffered h: [p][l][h][b]
__device__ float    g_part[NCTA * 2 * BSZ];                    // per-CTA LN partials
__device__ unsigned g_bar;

// ---------------- init: reset per launch (graph replays!) --------------------
__global__ void k_init() {
    int idx = blockIdx.x * blockDim.x + threadIdx.x;
    if (idx == 0) g_bar = 0u;
    for (int i = idx; i < 2 * LNUM * HDIM * BSZ; i += gridDim.x * blockDim.x)
        g_h[i] = 0.0f;
}

// ---------------- phase 1: Zi[l][t][h][b] = W_ih[l] @ x_t + b_ih ------------
__global__ __launch_bounds__(256) void k_gemm_zi(const float* __restrict__ Wih,
                                                 const float* __restrict__ x,
                                                 const float* __restrict__ bih) {
    __shared__ __align__(16) float Ws[32 * 132];  // [k][m] pad
    __shared__ __align__(16) float Xs[32 * 68];   // [k][n] pad

    const int l   = blockIdx.z;
    const int h0  = blockIdx.y * 128;
    const int n0g = blockIdx.x * 64;      // n = t*32 + b
    const int tid = threadIdx.x;
    const int m0  = (tid >> 4) * 4;
    const int c0  = (tid & 15) * 4;
    const float* Wbase = Wih + (size_t)l * HDIM * DDIM;

    float acc[8][4];
#pragma unroll
    for (int i = 0; i < 8; i++)
#pragma unroll
        for (int j = 0; j < 4; j++) acc[i][j] = 0.0f;

    for (int k0 = 0; k0 < DDIM; k0 += 32) {
        for (int i = tid; i < 4096; i += 256) {
            int m = i >> 5, k = i & 31;
            Ws[k * 132 + m] = Wbase[(size_t)(h0 + m) * DDIM + k0 + k];
        }
        for (int i = tid; i < 2048; i += 256) {
            int n = i >> 5, k = i & 31;
            int ng = n0g + n;
            int t = ng >> 5, b = ng & 31;
            Xs[k * 68 + n] = x[((size_t)b * TSTEPS + t) * DDIM + k0 + k];
        }
        __syncthreads();
#pragma unroll
        for (int k = 0; k < 32; k++) {
            float4 a0 = *(const float4*)(Ws + k * 132 + m0);
            float4 a1 = *(const float4*)(Ws + k * 132 + m0 + 64);
            float4 bv = *(const float4*)(Xs + k * 68 + c0);
            float av[8] = {a0.x, a0.y, a0.z, a0.w, a1.x, a1.y, a1.z, a1.w};
            float bb[4] = {bv.x, bv.y, bv.z, bv.w};
#pragma unroll
            for (int i = 0; i < 8; i++)
#pragma unroll
                for (int j = 0; j < 4; j++)
                    acc[i][j] = fmaf(av[i], bb[j], acc[i][j]);
        }
        __syncthreads();
    }

    float bi[8];
#pragma unroll
    for (int i = 0; i < 4; i++) {
        bi[i]     = bih[l * HDIM + h0 + m0 + i];
        bi[4 + i] = bih[l * HDIM + h0 + m0 + 64 + i];
    }
#pragma unroll
    for (int j = 0; j < 4; j++) {
        int ng = n0g + c0 + j;
        int t = ng >> 5, b = ng & 31;
        size_t base = ((size_t)(l * TSTEPS + t) * HDIM) * BSZ + b;
#pragma unroll
        for (int i = 0; i < 4; i++)
            g_A[base + (size_t)(h0 + m0 + i) * BSZ] = acc[i][j] + bi[i];
#pragma unroll
        for (int i = 0; i < 4; i++)
            g_A[base + (size_t)(h0 + m0 + 64 + i) * BSZ] = acc[4 + i][j] + bi[4 + i];
    }
}

// ---------------- LN over h for each (l,t,b), in place on g_A ---------------
__global__ __launch_bounds__(256) void k_ln(const float* __restrict__ gih,
                                            const float* __restrict__ beih) {
    const int lt = blockIdx.x;            // l*2048 + t
    const int l  = lt >> 11;
    const size_t base = (size_t)lt * HDIM * BSZ;
    const int tid = threadIdx.x;
    const int b = tid & 31, w = tid >> 5;

    float v[64];
    float s = 0.0f, q = 0.0f;
#pragma unroll
    for (int i = 0; i < 64; i++) {
        float xv = g_A[base + (size_t)(w * 64 + i) * BSZ + b];
        v[i] = xv;
        s += xv;
        q = fmaf(xv, xv, q);
    }
    __shared__ float rs[8][32], rq[8][32], mu_s[32], rstd_s[32];
    rs[w][b] = s; rq[w][b] = q;
    __syncthreads();
    if (w == 0) {
        float ss = 0.0f, qq = 0.0f;
#pragma unroll
        for (int j = 0; j < 8; j++) { ss += rs[j][b]; qq += rq[j][b]; }
        float mu = ss * (1.0f / HDIM);
        float var = qq * (1.0f / HDIM) - mu * mu;
        mu_s[b] = mu;
        rstd_s[b] = rsqrtf(var + EPS);
    }
    __syncthreads();
    float mu = mu_s[b], rstd = rstd_s[b];
#pragma unroll
    for (int i = 0; i < 64; i++) {
        int h = w * 64 + i;
        g_A[base + (size_t)h * BSZ + b] =
            (v[i] - mu) * rstd * gih[l * HDIM + h] + beih[l * HDIM + h];
    }
}

// ---------------- software grid barrier (cumulative target) ------------------
__device__ __forceinline__ void grid_sync(unsigned target) {
    __syncthreads();
    __threadfence();
    if (threadIdx.x == 0) {
        atomicAdd(&g_bar, 1u);
        volatile unsigned* bp = &g_bar;
        while (*bp < target) { __nanosleep(16); }
    }
    __syncthreads();
}

// ---------------- phase 2: persistent recurrence -----------------------------
// SMEM: W_s[16*512] | h_s[512*32] | red[2*4*32] | stat[2*32]
#define SMEM_RECUR ((16 * 512 + 512 * 32 + 2 * 4 * 32 + 2 * 32) * 4)

__global__ void __launch_bounds__(128, 1)
k_recur(const float* __restrict__ Whh, const float* __restrict__ bhh,
        const float* __restrict__ ghh, const float* __restrict__ behh) {
    extern __shared__ float sm[];
    float* W_s  = sm;                    // 8192 floats
    float* h_s  = sm + 8192;             // 16384 floats
    float* red  = sm + 8192 + 16384;     // 256 floats
    float* stat = red + 256;             // 64 floats

    const int cta = blockIdx.x;
    const int l   = cta >> 5;
    const int rb  = cta & 31;
    const int r0  = rb * 16;             // row base within layer
    const int tid = threadIdx.x;
    const int w   = tid >> 5;            // 4 warps, 4 rows each
    const int b   = tid & 31;

    // stationary W rows -> SMEM (local row lr = 4w+i)
    const float* Wl = Whh + (size_t)l * HDIM * HDIM + (size_t)r0 * HDIM;
    for (int i = tid; i < 16 * 512 / 4; i += 128)
        ((float4*)W_s)[i] = ((const float4*)Wl)[i];

    float bh[4], gh[4], beh[4];
#pragma unroll
    for (int i = 0; i < 4; i++) {
        int hh = r0 + 4 * w + i;
        bh[i]  = bhh[l * HDIM + hh];
        gh[i]  = ghh[l * HDIM + hh];
        beh[i] = behh[l * HDIM + hh];
    }

    unsigned nb = 0;
    for (int t = 0; t < TSTEPS; t++) {
        const int p = t & 1;
        const float* hin = g_h + (size_t)p * (LNUM * HDIM * BSZ) + (size_t)l * (HDIM * BSZ);

        // prefetch A = LN(zi) for our 4 outputs
        float a4[4];
#pragma unroll
        for (int i = 0; i < 4; i++) {
            int hh = r0 + 4 * w + i;
            a4[i] = g_A[(((size_t)l * TSTEPS + t) * HDIM + hh) * BSZ + b];
        }

        // load full layer-h into SMEM (L2-only loads: written by other SMs)
        for (int i = tid; i < HDIM * BSZ / 4; i += 128)
            ((float4*)h_s)[i] = __ldcg(((const float4*)hin) + i);
        __syncthreads();

        // zh for 4 rows, this lane's batch b
        float acc0 = 0.f, acc1 = 0.f, acc2 = 0.f, acc3 = 0.f;
        const float* Wr = W_s + (4 * w) * 512;
#pragma unroll 4
        for (int q = 0; q < 128; q++) {
            int k = 4 * q;
            float h0v = h_s[(k + 0) * 32 + b];
            float h1v = h_s[(k + 1) * 32 + b];
            float h2v = h_s[(k + 2) * 32 + b];
            float h3v = h_s[(k + 3) * 32 + b];
            float4 w0 = *(const float4*)(Wr + k);
            float4 w1 = *(const float4*)(Wr + 512 + k);
            float4 w2 = *(const float4*)(Wr + 1024 + k);
            float4 w3 = *(const float4*)(Wr + 1536 + k);
            acc0 = fmaf(w0.x, h0v, fmaf(w0.y, h1v, fmaf(w0.z, h2v, fmaf(w0.w, h3v, acc0))));
            acc1 = fmaf(w1.x, h0v, fmaf(w1.y, h1v, fmaf(w1.z, h2v, fmaf(w1.w, h3v, acc1))));
            acc2 = fmaf(w2.x, h0v, fmaf(w2.y, h1v, fmaf(w2.z, h2v, fmaf(w2.w, h3v, acc2))));
            acc3 = fmaf(w3.x, h0v, fmaf(w3.y, h1v, fmaf(w3.z, h2v, fmaf(w3.w, h3v, acc3))));
        }
        float z0 = acc0 + bh[0], z1 = acc1 + bh[1], z2 = acc2 + bh[2], z3 = acc3 + bh[3];

        // CTA-local LN partials over our 16 rows
        red[(0 * 4 + w) * 32 + b] = z0 + z1 + z2 + z3;
        red[(1 * 4 + w) * 32 + b] = fmaf(z0, z0, fmaf(z1, z1, fmaf(z2, z2, z3 * z3)));
        __syncthreads();
        if (w == 0) {
            float S = red[b] + red[32 + b] + red[64 + b] + red[96 + b];
            float Q = red[128 + b] + red[160 + b] + red[192 + b] + red[224 + b];
            g_part[((size_t)cta * 2 + 0) * 32 + b] = S;
            g_part[((size_t)cta * 2 + 1) * 32 + b] = Q;
        }
        grid_sync(++nb * NCTA);

        // combine 32 per-CTA partials of our layer (deterministic order)
        if (w == 0) {
            float S = 0.f, Q = 0.f;
#pragma unroll 8
            for (int cc = 0; cc < 32; cc++) {
                S += __ldcg(&g_part[((size_t)(l * 32 + cc) * 2 + 0) * 32 + b]);
                Q += __ldcg(&g_part[((size_t)(l * 32 + cc) * 2 + 1) * 32 + b]);
            }
            float mu = S * (1.0f / HDIM);
            float var = Q * (1.0f / HDIM) - mu * mu;
            stat[b] = mu;
            stat[32 + b] = rsqrtf(var + EPS);
        }
        __syncthreads();
        float mu = stat[b], rstd = stat[32 + b];

        float* hout = g_h + (size_t)(p ^ 1) * (LNUM * HDIM * BSZ) + (size_t)l * (HDIM * BSZ);
        float zz[4] = {z0, z1, z2, z3};
#pragma unroll
        for (int i = 0; i < 4; i++) {
            int hh = r0 + 4 * w + i;
            float hn = tanhf(a4[i] + (zz[i] - mu) * rstd * gh[i] + beh[i]);
            hout[(size_t)hh * 32 + b] = hn;
            if (l == 3) g_H3[((size_t)t * HDIM + hh) * BSZ + b] = hn;
        }
        grid_sync(++nb * NCTA);
    }
}

// ---------------- phase 3: out = h3 @ W_ho^T + b_ho + x ---------------------
__global__ __launch_bounds__(256) void k_gemm_out(const float* __restrict__ Who,
                                                  const float* __restrict__ bho,
                                                  const float* __restrict__ x,
                                                  float* __restrict__ out) {
    __shared__ __align__(16) float Ws[32 * 132];
    __shared__ __align__(16) float Xs[32 * 68];

    const int d0  = blockIdx.y * 128;
    const int n0g = blockIdx.x * 64;      // n = t*32 + b
    const int tid = threadIdx.x;
    const int m0  = (tid >> 4) * 4;
    const int c0  = (tid & 15) * 4;

    float acc[8][4];
#pragma unroll
    for (int i = 0; i < 8; i++)
#pragma unroll
        for (int j = 0; j < 4; j++) acc[i][j] = 0.0f;

    for (int k0 = 0; k0 < HDIM; k0 += 32) {
        for (int i = tid; i < 4096; i += 256) {
            int m = i >> 5, k = i & 31;
            Ws[k * 132 + m] = Who[(size_t)(d0 + m) * HDIM + k0 + k];
        }
        for (int i = tid; i < 2048; i += 256) {
            int k = i >> 6, n = i & 63;   // n fastest -> coalesced over b
            int ng = n0g + n;
            int t = ng >> 5, bb = ng & 31;
            Xs[k * 68 + n] = g_H3[((size_t)t * HDIM + k0 + k) * BSZ + bb];
        }
        __syncthreads();
#pragma unroll
        for (int k = 0; k < 32; k++) {
            float4 a0 = *(const float4*)(Ws + k * 132 + m0);
            float4 a1 = *(const float4*)(Ws + k * 132 + m0 + 64);
            float4 bv = *(const float4*)(Xs + k * 68 + c0);
            float av[8] = {a0.x, a0.y, a0.z, a0.w, a1.x, a1.y, a1.z, a1.w};
            float bb2[4] = {bv.x, bv.y, bv.z, bv.w};
#pragma unroll
            for (int i = 0; i < 8; i++)
#pragma unroll
                for (int j = 0; j < 4; j++)
                    acc[i][j] = fmaf(av[i], bb2[j], acc[i][j]);
        }
        __syncthreads();
    }

#pragma unroll
    for (int j = 0; j < 4; j++) {
        int ng = n0g + c0 + j;
        int t = ng >> 5, bb = ng & 31;
        size_t base = ((size_t)bb * TSTEPS + t) * DDIM;
#pragma unroll
        for (int i = 0; i < 4; i++) {
            int d = d0 + m0 + i;
            out[base + d] = acc[i][j] + bho[d] + x[base + d];
        }
#pragma unroll
        for (int i = 0; i < 4; i++) {
            int d = d0 + m0 + 64 + i;
            out[base + d] = acc[4 + i][j] + bho[d] + x[base + d];
        }
    }
}

// ---------------- h_final: [L,B,H] from g_h buffer 0 ([l][h][b]) -------------
__global__ void k_hfinal(float* __restrict__ out2) {
    int idx = blockIdx.x * 256 + threadIdx.x;   // 65536 total
    int l = idx >> 14;
    int rem = idx & 16383;
    int bb = rem >> 9;
    int hh = rem & 511;
    out2[idx] = g_h[(size_t)l * (HDIM * BSZ) + (size_t)hh * BSZ + bb];
}

// ---------------- launch -----------------------------------------------------
extern "C" void kernel_launch(void* const* d_in, const int* in_sizes, int n_in,
                              void* d_out, int out_size) {
    const float* x    = (const float*)d_in[0];
    const float* Wih  = (const float*)d_in[1];
    const float* bih  = (const float*)d_in[2];
    const float* gih  = (const float*)d_in[3];
    const float* beih = (const float*)d_in[4];
    const float* Whh  = (const float*)d_in[5];
    const float* bhh  = (const float*)d_in[6];
    const float* ghh  = (const float*)d_in[7];
    const float* behh = (const float*)d_in[8];
    const float* Who  = (const float*)d_in[9];
    const float* bho  = (const float*)d_in[10];
    float* out = (float*)d_out;

    cudaFuncSetAttribute(k_recur, cudaFuncAttributeMaxDynamicSharedMemorySize, SMEM_RECUR);

    k_init<<<64, 256>>>();
    dim3 g1(TSTEPS * BSZ / 64, HDIM / 128, LNUM);
    k_gemm_zi<<<g1, 256>>>(Wih, x, bih);
    k_ln<<<LNUM * TSTEPS, 256>>>(gih, beih);
    k_recur<<<NCTA, 128, SMEM_RECUR>>>(Whh, bhh, ghh, behh);
    dim3 g3(TSTEPS * BSZ / 64, DDIM / 128, 1);
    k_gemm_out<<<g3, 256>>>(Who, bho, x, out);
    k_hfinal<<<256, 256>>>(out + (size_t)BSZ * TSTEPS * DDIM);
}

// round 7
// speedup vs baseline: 1.0606x; 1.0606x over previous
#include <cuda_runtime.h>
#include <math.h>

#define LNUM 4
#define DDIM 512
#define HDIM 512
#define BSZ  32
#define TSTEPS 2048
#define EPS 1e-5f
#define NCTA 128   // 4 layers x 32 CTAs, 16 rows each

// ---------------- device scratch -------------------------------------------
__device__ float    g_A[(size_t)LNUM * TSTEPS * HDIM * BSZ];   // LN(zi): [l][t][h][b]
__device__ float    g_H3[(size_t)TSTEPS * HDIM * BSZ];         // layer-3 h: [t][h][b]
__device__ float    g_h[LNUM * HDIM * BSZ];                    // h state: [l][h][b]
__device__ float    g_part[LNUM * 32 * 2 * BSZ];               // [l][cta][S/Q][b]
__device__ unsigned g_bar4[4 * 32];                            // per-layer counters, 128B apart

// ---------------- init: reset per launch (graph replays!) -------------------
__global__ void k_init() {
    int idx = blockIdx.x * blockDim.x + threadIdx.x;
    if (idx < 4) g_bar4[idx * 32] = 0u;
    for (int i = idx; i < LNUM * HDIM * BSZ; i += gridDim.x * blockDim.x)
        g_h[i] = 0.0f;
}

// ---------------- phase 1: Zi[l][t][h][b] = W_ih[l] @ x_t + b_ih ------------
__global__ __launch_bounds__(256) void k_gemm_zi(const float* __restrict__ Wih,
                                                 const float* __restrict__ x,
                                                 const float* __restrict__ bih) {
    __shared__ __align__(16) float Ws[32 * 132];  // [k][m] pad
    __shared__ __align__(16) float Xs[32 * 68];   // [k][n] pad

    const int l   = blockIdx.z;
    const int h0  = blockIdx.y * 128;
    const int n0g = blockIdx.x * 64;      // n = t*32 + b
    const int tid = threadIdx.x;
    const int m0  = (tid >> 4) * 4;
    const int c0  = (tid & 15) * 4;
    const float* Wbase = Wih + (size_t)l * HDIM * DDIM;

    float acc[8][4];
#pragma unroll
    for (int i = 0; i < 8; i++)
#pragma unroll
        for (int j = 0; j < 4; j++) acc[i][j] = 0.0f;

    for (int k0 = 0; k0 < DDIM; k0 += 32) {
        for (int i = tid; i < 4096; i += 256) {
            int m = i >> 5, k = i & 31;
            Ws[k * 132 + m] = Wbase[(size_t)(h0 + m) * DDIM + k0 + k];
        }
        for (int i = tid; i < 2048; i += 256) {
            int n = i >> 5, k = i & 31;
            int ng = n0g + n;
            int t = ng >> 5, b = ng & 31;
            Xs[k * 68 + n] = x[((size_t)b * TSTEPS + t) * DDIM + k0 + k];
        }
        __syncthreads();
#pragma unroll
        for (int k = 0; k < 32; k++) {
            float4 a0 = *(const float4*)(Ws + k * 132 + m0);
            float4 a1 = *(const float4*)(Ws + k * 132 + m0 + 64);
            float4 bv = *(const float4*)(Xs + k * 68 + c0);
            float av[8] = {a0.x, a0.y, a0.z, a0.w, a1.x, a1.y, a1.z, a1.w};
            float bb[4] = {bv.x, bv.y, bv.z, bv.w};
#pragma unroll
            for (int i = 0; i < 8; i++)
#pragma unroll
                for (int j = 0; j < 4; j++)
                    acc[i][j] = fmaf(av[i], bb[j], acc[i][j]);
        }
        __syncthreads();
    }

    float bi[8];
#pragma unroll
    for (int i = 0; i < 4; i++) {
        bi[i]     = bih[l * HDIM + h0 + m0 + i];
        bi[4 + i] = bih[l * HDIM + h0 + m0 + 64 + i];
    }
#pragma unroll
    for (int j = 0; j < 4; j++) {
        int ng = n0g + c0 + j;
        int t = ng >> 5, b = ng & 31;
        size_t base = ((size_t)(l * TSTEPS + t) * HDIM) * BSZ + b;
#pragma unroll
        for (int i = 0; i < 4; i++)
            g_A[base + (size_t)(h0 + m0 + i) * BSZ] = acc[i][j] + bi[i];
#pragma unroll
        for (int i = 0; i < 4; i++)
            g_A[base + (size_t)(h0 + m0 + 64 + i) * BSZ] = acc[4 + i][j] + bi[4 + i];
    }
}

// ---------------- LN over h for each (l,t,b), in place on g_A ---------------
__global__ __launch_bounds__(256) void k_ln(const float* __restrict__ gih,
                                            const float* __restrict__ beih) {
    const int lt = blockIdx.x;            // l*2048 + t
    const int l  = lt >> 11;
    const size_t base = (size_t)lt * HDIM * BSZ;
    const int tid = threadIdx.x;
    const int b = tid & 31, w = tid >> 5;

    float v[64];
    float s = 0.0f, q = 0.0f;
#pragma unroll
    for (int i = 0; i < 64; i++) {
        float xv = g_A[base + (size_t)(w * 64 + i) * BSZ + b];
        v[i] = xv;
        s += xv;
        q = fmaf(xv, xv, q);
    }
    __shared__ float rs[8][32], rq[8][32], mu_s[32], rstd_s[32];
    rs[w][b] = s; rq[w][b] = q;
    __syncthreads();
    if (w == 0) {
        float ss = 0.0f, qq = 0.0f;
#pragma unroll
        for (int j = 0; j < 8; j++) { ss += rs[j][b]; qq += rq[j][b]; }
        float mu = ss * (1.0f / HDIM);
        float var = qq * (1.0f / HDIM) - mu * mu;
        mu_s[b] = mu;
        rstd_s[b] = rsqrtf(var + EPS);
    }
    __syncthreads();
    float mu = mu_s[b], rstd = rstd_s[b];
#pragma unroll
    for (int i = 0; i < 64; i++) {
        int h = w * 64 + i;
        g_A[base + (size_t)h * BSZ + b] =
            (v[i] - mu) * rstd * gih[l * HDIM + h] + beih[l * HDIM + h];
    }
}

// ---------------- phase 2: persistent recurrence -----------------------------
// SMEM floats: W_s 8192 | h_s 16384 | red 1024 | red2 512 | stat 64
#define SMEM_RECUR ((8192 + 16384 + 1024 + 512 + 64) * 4)

__global__ void __launch_bounds__(256, 1)
k_recur(const float* __restrict__ Whh, const float* __restrict__ bhh,
        const float* __restrict__ ghh, const float* __restrict__ behh) {
    extern __shared__ float sm[];
    float* W_s  = sm;                    // [k][16 rows]  (transposed)
    float* h_s  = sm + 8192;             // [k][32 b]
    float* red  = h_s + 16384;           // [2 halves][16 rows][32 b]
    float* red2 = red + 1024;            // [8 warps][2][32 b]
    float* stat = red2 + 512;            // [2][32 b]

    const int cta  = blockIdx.x;
    const int l    = cta >> 5;
    const int cl   = cta & 31;           // cta within layer
    const int r0   = cl * 16;
    const int tid  = threadIdx.x;
    const int w    = tid >> 5;
    const int b    = tid & 31;
    const int half = w >> 2;             // k half: 0 -> [0,256), 1 -> [256,512)
    const int quad = w & 3;              // row quad: rows 4*quad..4*quad+3
    const int rA   = w;                  // LN-stage rows: rA and rA+8

    // stationary W rows -> SMEM, transposed to [k][row]
    const float* Wl = Whh + (size_t)l * HDIM * HDIM + (size_t)r0 * HDIM;
    for (int idx = tid; idx < 16 * 512; idx += 256) {
        int r = idx >> 9, k = idx & 511;
        W_s[k * 16 + r] = Wl[r * 512 + k];
    }

    const float bhA = bhh[l * HDIM + r0 + rA],  bhB = bhh[l * HDIM + r0 + rA + 8];
    const float ghA = ghh[l * HDIM + r0 + rA],  ghB = ghh[l * HDIM + r0 + rA + 8];
    const float beA = behh[l * HDIM + r0 + rA], beB = behh[l * HDIM + r0 + rA + 8];

    unsigned* barp = &g_bar4[l * 32];
    float* hbuf = g_h + (size_t)l * (HDIM * BSZ);
    const float* partL = g_part + (size_t)l * 32 * 2 * BSZ;

    __syncthreads();

    unsigned base_cnt = 0;
    for (int t = 0; t < TSTEPS; t++) {
        // ---- load h_{t-1} slab (written by other SMs -> bypass L1) ----
        for (int i = tid; i < HDIM * BSZ / 4; i += 256)
            ((float4*)h_s)[i] = __ldcg(((const float4*)hbuf) + i);

        // prefetch a_t for this thread's 2 rows (consumed after barrier 1)
        const float* aptr = g_A + ((size_t)l * TSTEPS + t) * HDIM * BSZ;
        float aA = __ldcs(aptr + (size_t)(r0 + rA) * BSZ + b);
        float aB = __ldcs(aptr + (size_t)(r0 + rA + 8) * BSZ + b);
        __syncthreads();

        // ---- matvec: warp (half,quad) -> rows 4*quad..+3 over k-half ----
        float a0 = 0.f, a1 = 0.f, a2 = 0.f, a3 = 0.f;
        {
            const int k0 = half * 256;
#pragma unroll 8
            for (int k = k0; k < k0 + 256; k++) {
                float  hv = h_s[k * 32 + b];
                float4 wv = *(const float4*)(W_s + k * 16 + 4 * quad);
                a0 = fmaf(wv.x, hv, a0);
                a1 = fmaf(wv.y, hv, a1);
                a2 = fmaf(wv.z, hv, a2);
                a3 = fmaf(wv.w, hv, a3);
            }
        }
        {
            float* rr = red + half * 512 + (4 * quad) * 32 + b;
            rr[0] = a0; rr[32] = a1; rr[64] = a2; rr[96] = a3;
        }
        __syncthreads();

        // ---- combine k-halves; z kept in registers; CTA LN partials ----
        float zA = red[rA * 32 + b]       + red[512 + rA * 32 + b]       + bhA;
        float zB = red[(rA + 8) * 32 + b] + red[512 + (rA + 8) * 32 + b] + bhB;
        red2[(w * 2 + 0) * 32 + b] = zA + zB;
        red2[(w * 2 + 1) * 32 + b] = fmaf(zA, zA, zB * zB);
        __syncthreads();
        if (w == 0) {
            float S = 0.f, Q = 0.f;
#pragma unroll
            for (int j = 0; j < 8; j++) { S += red2[(j * 2) * 32 + b]; Q += red2[(j * 2 + 1) * 32 + b]; }
            g_part[(((size_t)l * 32 + cl) * 2 + 0) * 32 + b] = S;
            g_part[(((size_t)l * 32 + cl) * 2 + 1) * 32 + b] = Q;
            __threadfence();
        }
        __syncthreads();

        // ---- barrier 1 (per-layer, 32 CTAs) ----
        if (tid == 0) {
            atomicAdd(barp, 1u);
            volatile unsigned* vp = (volatile unsigned*)barp;
            while (*vp < base_cnt + 32) { }
            __threadfence();
        }
        __syncthreads();

        // ---- stats: 8 warps x 4 CTAs, fixed deterministic tree ----
        {
            float S = 0.f, Q = 0.f;
#pragma unroll
            for (int j = 0; j < 4; j++) {
                int cc = w * 4 + j;
                S += __ldcg(partL + (cc * 2 + 0) * 32 + b);
                Q += __ldcg(partL + (cc * 2 + 1) * 32 + b);
            }
            red2[(w * 2 + 0) * 32 + b] = S;
            red2[(w * 2 + 1) * 32 + b] = Q;
        }
        __syncthreads();
        if (w == 0) {
            float S = 0.f, Q = 0.f;
#pragma unroll
            for (int j = 0; j < 8; j++) { S += red2[(j * 2) * 32 + b]; Q += red2[(j * 2 + 1) * 32 + b]; }
            float mu = S * (1.0f / HDIM);
            float var = Q * (1.0f / HDIM) - mu * mu;
            stat[b] = mu;
            stat[32 + b] = rsqrtf(var + EPS);
        }
        __syncthreads();

        // ---- h_t for own rows ----
        float mu = stat[b], rstd = stat[32 + b];
        float hA = tanhf(aA + (zA - mu) * rstd * ghA + beA);
        float hB = tanhf(aB + (zB - mu) * rstd * ghB + beB);
        hbuf[(size_t)(r0 + rA) * 32 + b]     = hA;
        hbuf[(size_t)(r0 + rA + 8) * 32 + b] = hB;
        if (l == 3) {
            float* hp = g_H3 + (size_t)t * HDIM * BSZ;
            hp[(size_t)(r0 + rA) * 32 + b]     = hA;
            hp[(size_t)(r0 + rA + 8) * 32 + b] = hB;
        }
        __threadfence();
        __syncthreads();

        // ---- barrier 2 ----
        if (tid == 0) {
            atomicAdd(barp, 1u);
            volatile unsigned* vp = (volatile unsigned*)barp;
            while (*vp < base_cnt + 64) { }
            __threadfence();
        }
        __syncthreads();
        base_cnt += 64;
    }
}

// ---------------- phase 3: out = h3 @ W_ho^T + b_ho + x ---------------------
__global__ __launch_bounds__(256) void k_gemm_out(const float* __restrict__ Who,
                                                  const float* __restrict__ bho,
                                                  const float* __restrict__ x,
                                                  float* __restrict__ out) {
    __shared__ __align__(16) float Ws[32 * 132];
    __shared__ __align__(16) float Xs[32 * 68];

    const int d0  = blockIdx.y * 128;
    const int n0g = blockIdx.x * 64;      // n = t*32 + b
    const int tid = threadIdx.x;
    const int m0  = (tid >> 4) * 4;
    const int c0  = (tid & 15) * 4;

    float acc[8][4];
#pragma unroll
    for (int i = 0; i < 8; i++)
#pragma unroll
        for (int j = 0; j < 4; j++) acc[i][j] = 0.0f;

    for (int k0 = 0; k0 < HDIM; k0 += 32) {
        for (int i = tid; i < 4096; i += 256) {
            int m = i >> 5, k = i & 31;
            Ws[k * 132 + m] = Who[(size_t)(d0 + m) * HDIM + k0 + k];
        }
        for (int i = tid; i < 2048; i += 256) {
            int k = i >> 6, n = i & 63;   // n fastest -> coalesced over b
            int ng = n0g + n;
            int t = ng >> 5, bb = ng & 31;
            Xs[k * 68 + n] = g_H3[((size_t)t * HDIM + k0 + k) * BSZ + bb];
        }
        __syncthreads();
#pragma unroll
        for (int k = 0; k < 32; k++) {
            float4 a0 = *(const float4*)(Ws + k * 132 + m0);
            float4 a1 = *(const float4*)(Ws + k * 132 + m0 + 64);
            float4 bv = *(const float4*)(Xs + k * 68 + c0);
            float av[8] = {a0.x, a0.y, a0.z, a0.w, a1.x, a1.y, a1.z, a1.w};
            float bb2[4] = {bv.x, bv.y, bv.z, bv.w};
#pragma unroll
            for (int i = 0; i < 8; i++)
#pragma unroll
                for (int j = 0; j < 4; j++)
                    acc[i][j] = fmaf(av[i], bb2[j], acc[i][j]);
        }
        __syncthreads();
    }

#pragma unroll
    for (int j = 0; j < 4; j++) {
        int ng = n0g + c0 + j;
        int t = ng >> 5, bb = ng & 31;
        size_t base = ((size_t)bb * TSTEPS + t) * DDIM;
#pragma unroll
        for (int i = 0; i < 4; i++) {
            int d = d0 + m0 + i;
            out[base + d] = acc[i][j] + bho[d] + x[base + d];
        }
#pragma unroll
        for (int i = 0; i < 4; i++) {
            int d = d0 + m0 + 64 + i;
            out[base + d] = acc[4 + i][j] + bho[d] + x[base + d];
        }
    }
}

// ---------------- h_final: [L,B,H] from g_h ([l][h][b]) ---------------------
__global__ void k_hfinal(float* __restrict__ out2) {
    int idx = blockIdx.x * 256 + threadIdx.x;   // 65536 total
    int l = idx >> 14;
    int rem = idx & 16383;
    int bb = rem >> 9;
    int hh = rem & 511;
    out2[idx] = g_h[(size_t)l * (HDIM * BSZ) + (size_t)hh * BSZ + bb];
}

// ---------------- launch -----------------------------------------------------
extern "C" void kernel_launch(void* const* d_in, const int* in_sizes, int n_in,
                              void* d_out, int out_size) {
    const float* x    = (const float*)d_in[0];
    const float* Wih  = (const float*)d_in[1];
    const float* bih  = (const float*)d_in[2];
    const float* gih  = (const float*)d_in[3];
    const float* beih = (const float*)d_in[4];
    const float* Whh  = (const float*)d_in[5];
    const float* bhh  = (const float*)d_in[6];
    const float* ghh  = (const float*)d_in[7];
    const float* behh = (const float*)d_in[8];
    const float* Who  = (const float*)d_in[9];
    const float* bho  = (const float*)d_in[10];
    float* out = (float*)d_out;

    cudaFuncSetAttribute(k_recur, cudaFuncAttributeMaxDynamicSharedMemorySize, SMEM_RECUR);

    k_init<<<64, 256>>>();
    dim3 g1(TSTEPS * BSZ / 64, HDIM / 128, LNUM);
    k_gemm_zi<<<g1, 256>>>(Wih, x, bih);
    k_ln<<<LNUM * TSTEPS, 256>>>(gih, beih);
    k_recur<<<NCTA, 256, SMEM_RECUR>>>(Whh, bhh, ghh, behh);
    dim3 g3(TSTEPS * BSZ / 64, DDIM / 128, 1);
    k_gemm_out<<<g3, 256>>>(Who, bho, x, out);
    k_hfinal<<<256, 256>>>(out + (size_t)BSZ * TSTEPS * DDIM);
}

// round 8
// speedup vs baseline: 1.0833x; 1.0213x over previous
#include <cuda_runtime.h>
#include <math.h>

#define LNUM 4
#define DDIM 512
#define HDIM 512
#define BSZ  32
#define TSTEPS 2048
#define EPS 1e-5f
#define NCTA 128   // 4 layers x 32 CTAs, 16 rows each

// ---------------- device scratch -------------------------------------------
__device__ float g_A[(size_t)LNUM * TSTEPS * HDIM * BSZ];   // LN(zi): [l][t][h][b]
__device__ float g_H3[(size_t)TSTEPS * HDIM * BSZ];         // layer-3 h: [t][h][b]
__device__ float g_h[2 * LNUM * HDIM * BSZ];                // h^s in buf[s&1]: [p][l][h][b]
__device__ float g_part[2 * LNUM * 32 * 2 * BSZ];           // [p][l][cta][S/Q][b]
__device__ __align__(128) unsigned g_hflag[LNUM * 32];      // per-layer 128B line
__device__ __align__(128) unsigned g_pflag[LNUM * 32];

// ---------------- flag primitives ------------------------------------------
__device__ __forceinline__ unsigned ld_acq(const unsigned* p) {
    unsigned v;
    asm volatile("ld.acquire.gpu.global.u32 %0, [%1];" : "=r"(v) : "l"(p) : "memory");
    return v;
}
__device__ __forceinline__ void red_add1(unsigned* p) {
    asm volatile("red.relaxed.gpu.global.add.u32 [%0], 1;" :: "l"(p) : "memory");
}
// all 32 lanes poll 16 flags (duplicated x2) in one 128B line
__device__ __forceinline__ void poll16(const unsigned* line, int half, unsigned target) {
    const unsigned* f = line + half * 16 + (threadIdx.x & 15);
    if (__all_sync(0xffffffffu, ld_acq(f) >= target)) return;
    while (!__all_sync(0xffffffffu, ld_acq(f) >= target)) __nanosleep(32);
}
__device__ __forceinline__ void poll32(const unsigned* line, unsigned target) {
    const unsigned* f = line + (threadIdx.x & 31);
    if (__all_sync(0xffffffffu, ld_acq(f) >= target)) return;
    while (!__all_sync(0xffffffffu, ld_acq(f) >= target)) __nanosleep(32);
}

// ---------------- init: reset per launch (graph replays!) -------------------
__global__ void k_init() {
    int idx = blockIdx.x * blockDim.x + threadIdx.x;
    if (idx < LNUM * 32) { g_hflag[idx] = 0u; g_pflag[idx] = 0u; }
    for (int i = idx; i < 2 * LNUM * HDIM * BSZ; i += gridDim.x * blockDim.x)
        g_h[i] = 0.0f;
}

// ---------------- phase 1: Zi[l][t][h][b] = W_ih[l] @ x_t + b_ih ------------
__global__ __launch_bounds__(256) void k_gemm_zi(const float* __restrict__ Wih,
                                                 const float* __restrict__ x,
                                                 const float* __restrict__ bih) {
    __shared__ __align__(16) float Ws[32 * 132];  // [k][m] pad
    __shared__ __align__(16) float Xs[32 * 68];   // [k][n] pad

    const int l   = blockIdx.z;
    const int h0  = blockIdx.y * 128;
    const int n0g = blockIdx.x * 64;      // n = t*32 + b
    const int tid = threadIdx.x;
    const int m0  = (tid >> 4) * 4;
    const int c0  = (tid & 15) * 4;
    const float* Wbase = Wih + (size_t)l * HDIM * DDIM;

    float acc[8][4];
#pragma unroll
    for (int i = 0; i < 8; i++)
#pragma unroll
        for (int j = 0; j < 4; j++) acc[i][j] = 0.0f;

    for (int k0 = 0; k0 < DDIM; k0 += 32) {
        for (int i = tid; i < 4096; i += 256) {
            int m = i >> 5, k = i & 31;
            Ws[k * 132 + m] = Wbase[(size_t)(h0 + m) * DDIM + k0 + k];
        }
        for (int i = tid; i < 2048; i += 256) {
            int n = i >> 5, k = i & 31;
            int ng = n0g + n;
            int t = ng >> 5, b = ng & 31;
            Xs[k * 68 + n] = x[((size_t)b * TSTEPS + t) * DDIM + k0 + k];
        }
        __syncthreads();
#pragma unroll
        for (int k = 0; k < 32; k++) {
            float4 a0 = *(const float4*)(Ws + k * 132 + m0);
            float4 a1 = *(const float4*)(Ws + k * 132 + m0 + 64);
            float4 bv = *(const float4*)(Xs + k * 68 + c0);
            float av[8] = {a0.x, a0.y, a0.z, a0.w, a1.x, a1.y, a1.z, a1.w};
            float bb[4] = {bv.x, bv.y, bv.z, bv.w};
#pragma unroll
            for (int i = 0; i < 8; i++)
#pragma unroll
                for (int j = 0; j < 4; j++)
                    acc[i][j] = fmaf(av[i], bb[j], acc[i][j]);
        }
        __syncthreads();
    }

    float bi[8];
#pragma unroll
    for (int i = 0; i < 4; i++) {
        bi[i]     = bih[l * HDIM + h0 + m0 + i];
        bi[4 + i] = bih[l * HDIM + h0 + m0 + 64 + i];
    }
#pragma unroll
    for (int j = 0; j < 4; j++) {
        int ng = n0g + c0 + j;
        int t = ng >> 5, b = ng & 31;
        size_t base = ((size_t)(l * TSTEPS + t) * HDIM) * BSZ + b;
#pragma unroll
        for (int i = 0; i < 4; i++)
            g_A[base + (size_t)(h0 + m0 + i) * BSZ] = acc[i][j] + bi[i];
#pragma unroll
        for (int i = 0; i < 4; i++)
            g_A[base + (size_t)(h0 + m0 + 64 + i) * BSZ] = acc[4 + i][j] + bi[4 + i];
    }
}

// ---------------- LN over h for each (l,t,b), in place on g_A ---------------
__global__ __launch_bounds__(256) void k_ln(const float* __restrict__ gih,
                                            const float* __restrict__ beih) {
    const int lt = blockIdx.x;            // l*2048 + t
    const int l  = lt >> 11;
    const size_t base = (size_t)lt * HDIM * BSZ;
    const int tid = threadIdx.x;
    const int b = tid & 31, w = tid >> 5;

    float v[64];
    float s = 0.0f, q = 0.0f;
#pragma unroll
    for (int i = 0; i < 64; i++) {
        float xv = g_A[base + (size_t)(w * 64 + i) * BSZ + b];
        v[i] = xv;
        s += xv;
        q = fmaf(xv, xv, q);
    }
    __shared__ float rs[8][32], rq[8][32], mu_s[32], rstd_s[32];
    rs[w][b] = s; rq[w][b] = q;
    __syncthreads();
    if (w == 0) {
        float ss = 0.0f, qq = 0.0f;
#pragma unroll
        for (int j = 0; j < 8; j++) { ss += rs[j][b]; qq += rq[j][b]; }
        float mu = ss * (1.0f / HDIM);
        float var = qq * (1.0f / HDIM) - mu * mu;
        mu_s[b] = mu;
        rstd_s[b] = rsqrtf(var + EPS);
    }
    __syncthreads();
    float mu = mu_s[b], rstd = rstd_s[b];
#pragma unroll
    for (int i = 0; i < 64; i++) {
        int h = w * 64 + i;
        g_A[base + (size_t)h * BSZ + b] =
            (v[i] - mu) * rstd * gih[l * HDIM + h] + beih[l * HDIM + h];
    }
}

// ---------------- phase 2: barrier-free persistent recurrence ---------------
// SMEM floats: W_s 8192 | h_s 16384 | red 1024 | red2 512 | stat 64
#define SMEM_RECUR ((8192 + 16384 + 1024 + 512 + 64) * 4)

__global__ void __launch_bounds__(256, 1)
k_recur(const float* __restrict__ Whh, const float* __restrict__ bhh,
        const float* __restrict__ ghh, const float* __restrict__ behh) {
    extern __shared__ float sm[];
    float* W_s  = sm;                    // [k][16 rows] transposed
    float* h_s  = sm + 8192;             // [k][32 b]
    float* red  = h_s + 16384;           // [kq 0/1][16 rows][32 b]
    float* red2 = red + 1024;            // [8 warps][2][32 b]
    float* stat = red2 + 512;            // [2][32 b]

    const int cta = blockIdx.x;
    const int l   = cta >> 5;
    const int cl  = cta & 31;
    const int r0  = cl * 16;
    const int tid = threadIdx.x;
    const int w   = tid >> 5;
    const int b   = tid & 31;
    const int q   = w & 3;               // row quad: rows 4q..4q+3
    const int kq  = w >> 2;              // k quarter within each half

    // stationary W rows -> SMEM transposed [k][row]
    const float* Wl = Whh + (size_t)l * HDIM * HDIM + (size_t)r0 * HDIM;
    for (int idx = tid; idx < 16 * 512; idx += 256) {
        int r = idx >> 9, k = idx & 511;
        W_s[k * 16 + r] = Wl[r * 512 + k];
    }

    const float bhA = bhh[l * HDIM + r0 + w],  bhB = bhh[l * HDIM + r0 + w + 8];
    const float ghA = ghh[l * HDIM + r0 + w],  ghB = ghh[l * HDIM + r0 + w + 8];
    const float beA = behh[l * HDIM + r0 + w], beB = behh[l * HDIM + r0 + w + 8];

    const unsigned* hline = g_hflag + l * 32;
    const unsigned* pline = g_pflag + l * 32;
    unsigned* my_hflag = g_hflag + l * 32 + cl;
    unsigned* my_pflag = g_pflag + l * 32 + cl;

    __syncthreads();

    for (int s = 0; s < TSTEPS; s++) {
        const float* hin = g_h + (size_t)(s & 1) * (LNUM * HDIM * BSZ) + (size_t)l * (HDIM * BSZ);
        float*       hout = g_h + (size_t)((s + 1) & 1) * (LNUM * HDIM * BSZ) + (size_t)l * (HDIM * BSZ);
        float* pb = g_part + (size_t)((s & 1) * LNUM + l) * (32 * 2 * BSZ);

        // prefetch a_t for own 2 rows
        const float* aptr = g_A + ((size_t)l * TSTEPS + s) * HDIM * BSZ;
        float aA = __ldcs(aptr + (size_t)(r0 + w) * BSZ + b);
        float aB = __ldcs(aptr + (size_t)(r0 + w + 8) * BSZ + b);

        // ---- half 0: wait producers 0..15, load k[0,256), matvec ----
        poll16(hline, 0, (unsigned)s);
        for (int i = tid; i < 2048; i += 256)
            ((float4*)h_s)[i] = __ldcg(((const float4*)hin) + i);
        __syncthreads();   // S1

        float a0 = 0.f, a1 = 0.f, a2 = 0.f, a3 = 0.f;
        {
            const int kb = kq * 128;
#pragma unroll 8
            for (int k = kb; k < kb + 128; k++) {
                float  hv = h_s[k * 32 + b];
                float4 wv = *(const float4*)(W_s + k * 16 + 4 * q);
                a0 = fmaf(wv.x, hv, a0);
                a1 = fmaf(wv.y, hv, a1);
                a2 = fmaf(wv.z, hv, a2);
                a3 = fmaf(wv.w, hv, a3);
            }
        }

        // ---- half 1: wait producers 16..31, load k[256,512), matvec ----
        poll16(hline, 1, (unsigned)s);
        for (int i = tid; i < 2048; i += 256)
            ((float4*)(h_s + 8192))[i] = __ldcg(((const float4*)(hin + 8192)) + i);
        __syncthreads();   // S2

        {
            const int kb = 256 + kq * 128;
#pragma unroll 8
            for (int k = kb; k < kb + 128; k++) {
                float  hv = h_s[k * 32 + b];
                float4 wv = *(const float4*)(W_s + k * 16 + 4 * q);
                a0 = fmaf(wv.x, hv, a0);
                a1 = fmaf(wv.y, hv, a1);
                a2 = fmaf(wv.z, hv, a2);
                a3 = fmaf(wv.w, hv, a3);
            }
        }
        {
            float* rr = red + kq * 512 + (4 * q) * 32 + b;
            rr[0] = a0; rr[32] = a1; rr[64] = a2; rr[96] = a3;
        }
        __syncthreads();   // S3

        // ---- z for own 2 rows; CTA LN partials ----
        float zA = red[w * 32 + b]       + red[512 + w * 32 + b]       + bhA;
        float zB = red[(w + 8) * 32 + b] + red[512 + (w + 8) * 32 + b] + bhB;
        red2[(w * 2 + 0) * 32 + b] = zA + zB;
        red2[(w * 2 + 1) * 32 + b] = fmaf(zA, zA, zB * zB);
        __syncthreads();   // S4

        // ---- warp 0 publishes CTA partials + pflag (release) ----
        if (w == 0) {
            float S = 0.f, Q = 0.f;
#pragma unroll
            for (int j = 0; j < 8; j++) { S += red2[(j * 2) * 32 + b]; Q += red2[(j * 2 + 1) * 32 + b]; }
            pb[cl * 64 + b]      = S;
            pb[cl * 64 + 32 + b] = Q;
            __threadfence();
            __syncwarp();
            if (b == 0) red_add1(my_pflag);
        }

        // ---- all warps wait for layer partials, reduce (fixed order) ----
        poll32(pline, (unsigned)(s + 1));
        {
            float S = 0.f, Q = 0.f;
#pragma unroll
            for (int j = 0; j < 4; j++) {
                int cc = w * 4 + j;
                S += __ldcg(pb + cc * 64 + b);
                Q += __ldcg(pb + cc * 64 + 32 + b);
            }
            __syncthreads();   // S5 (red2 safely consumed by w0 before its pflag release)
            red2[(w * 2 + 0) * 32 + b] = S;
            red2[(w * 2 + 1) * 32 + b] = Q;
        }
        __syncthreads();   // S6
        if (w == 0) {
            float S = 0.f, Q = 0.f;
#pragma unroll
            for (int j = 0; j < 8; j++) { S += red2[(j * 2) * 32 + b]; Q += red2[(j * 2 + 1) * 32 + b]; }
            float mu = S * (1.0f / HDIM);
            float var = Q * (1.0f / HDIM) - mu * mu;
            stat[b] = mu;
            stat[32 + b] = rsqrtf(var + EPS);
        }
        __syncthreads();   // S7

        // ---- h^{s+1} for own rows; publish hflag (release) ----
        float mu = stat[b], rstd = stat[32 + b];
        float hA = tanhf(aA + (zA - mu) * rstd * ghA + beA);
        float hB = tanhf(aB + (zB - mu) * rstd * ghB + beB);
        hout[(size_t)(r0 + w) * 32 + b]     = hA;
        hout[(size_t)(r0 + w + 8) * 32 + b] = hB;
        if (l == 3) {
            float* hp = g_H3 + (size_t)s * HDIM * BSZ;
            hp[(size_t)(r0 + w) * 32 + b]     = hA;
            hp[(size_t)(r0 + w + 8) * 32 + b] = hB;
        }
        __threadfence();
        __syncthreads();   // S8
        if (tid == 0) red_add1(my_hflag);
    }
}

// ---------------- phase 3: out = h3 @ W_ho^T + b_ho + x ---------------------
__global__ __launch_bounds__(256) void k_gemm_out(const float* __restrict__ Who,
                                                  const float* __restrict__ bho,
                                                  const float* __restrict__ x,
                                                  float* __restrict__ out) {
    __shared__ __align__(16) float Ws[32 * 132];
    __shared__ __align__(16) float Xs[32 * 68];

    const int d0  = blockIdx.y * 128;
    const int n0g = blockIdx.x * 64;      // n = t*32 + b
    const int tid = threadIdx.x;
    const int m0  = (tid >> 4) * 4;
    const int c0  = (tid & 15) * 4;

    float acc[8][4];
#pragma unroll
    for (int i = 0; i < 8; i++)
#pragma unroll
        for (int j = 0; j < 4; j++) acc[i][j] = 0.0f;

    for (int k0 = 0; k0 < HDIM; k0 += 32) {
        for (int i = tid; i < 4096; i += 256) {
            int m = i >> 5, k = i & 31;
            Ws[k * 132 + m] = Who[(size_t)(d0 + m) * HDIM + k0 + k];
        }
        for (int i = tid; i < 2048; i += 256) {
            int k = i >> 6, n = i & 63;
            int ng = n0g + n;
            int t = ng >> 5, bb = ng & 31;
            Xs[k * 68 + n] = g_H3[((size_t)t * HDIM + k0 + k) * BSZ + bb];
        }
        __syncthreads();
#pragma unroll
        for (int k = 0; k < 32; k++) {
            float4 a0 = *(const float4*)(Ws + k * 132 + m0);
            float4 a1 = *(const float4*)(Ws + k * 132 + m0 + 64);
            float4 bv = *(const float4*)(Xs + k * 68 + c0);
            float av[8] = {a0.x, a0.y, a0.z, a0.w, a1.x, a1.y, a1.z, a1.w};
            float bb2[4] = {bv.x, bv.y, bv.z, bv.w};
#pragma unroll
            for (int i = 0; i < 8; i++)
#pragma unroll
                for (int j = 0; j < 4; j++)
                    acc[i][j] = fmaf(av[i], bb2[j], acc[i][j]);
        }
        __syncthreads();
    }

#pragma unroll
    for (int j = 0; j < 4; j++) {
        int ng = n0g + c0 + j;
        int t = ng >> 5, bb = ng & 31;
        size_t base = ((size_t)bb * TSTEPS + t) * DDIM;
#pragma unroll
        for (int i = 0; i < 4; i++) {
            int d = d0 + m0 + i;
            out[base + d] = acc[i][j] + bho[d] + x[base + d];
        }
#pragma unroll
        for (int i = 0; i < 4; i++) {
            int d = d0 + m0 + 64 + i;
            out[base + d] = acc[4 + i][j] + bho[d] + x[base + d];
        }
    }
}

// ---------------- h_final: [L,B,H] from g_h buf[0] (h^2048, 2048&1==0) ------
__global__ void k_hfinal(float* __restrict__ out2) {
    int idx = blockIdx.x * 256 + threadIdx.x;   // 65536 total
    int l = idx >> 14;
    int rem = idx & 16383;
    int bb = rem >> 9;
    int hh = rem & 511;
    out2[idx] = g_h[(size_t)l * (HDIM * BSZ) + (size_t)hh * BSZ + bb];
}

// ---------------- launch -----------------------------------------------------
extern "C" void kernel_launch(void* const* d_in, const int* in_sizes, int n_in,
                              void* d_out, int out_size) {
    const float* x    = (const float*)d_in[0];
    const float* Wih  = (const float*)d_in[1];
    const float* bih  = (const float*)d_in[2];
    const float* gih  = (const float*)d_in[3];
    const float* beih = (const float*)d_in[4];
    const float* Whh  = (const float*)d_in[5];
    const float* bhh  = (const float*)d_in[6];
    const float* ghh  = (const float*)d_in[7];
    const float* behh = (const float*)d_in[8];
    const float* Who  = (const float*)d_in[9];
    const float* bho  = (const float*)d_in[10];
    float* out = (float*)d_out;

    cudaFuncSetAttribute(k_recur, cudaFuncAttributeMaxDynamicSharedMemorySize, SMEM_RECUR);

    k_init<<<64, 256>>>();
    dim3 g1(TSTEPS * BSZ / 64, HDIM / 128, LNUM);
    k_gemm_zi<<<g1, 256>>>(Wih, x, bih);
    k_ln<<<LNUM * TSTEPS, 256>>>(gih, beih);
    k_recur<<<NCTA, 256, SMEM_RECUR>>>(Whh, bhh, ghh, behh);
    dim3 g3(TSTEPS * BSZ / 64, DDIM / 128, 1);
    k_gemm_out<<<g3, 256>>>(Who, bho, x, out);
    k_hfinal<<<256, 256>>>(out + (size_t)BSZ * TSTEPS * DDIM);
}

// round 9
// speedup vs baseline: 1.1240x; 1.0376x over previous
#include <cuda_runtime.h>
#include <math.h>

#define LNUM 4
#define DDIM 512
#define HDIM 512
#define BSZ  32
#define TSTEPS 2048
#define EPS 1e-5f
#define NCTA 128   // 4 layers x 32 CTAs, 16 rows each

// ---------------- device scratch -------------------------------------------
__device__ float g_A[(size_t)LNUM * TSTEPS * HDIM * BSZ];   // LN(zi): [l][t][h][b]
__device__ float g_H3[(size_t)TSTEPS * HDIM * BSZ];         // layer-3 h: [t][h][b]
__device__ float g_h[2 * LNUM * HDIM * BSZ];                // h^s in buf[s&1]: [p][l][h][b]
__device__ float g_part[2 * LNUM * 32 * 2 * BSZ];           // [p][l][cta][S/Q][b]
__device__ __align__(128) unsigned g_hflag[LNUM * 32];      // per-layer 128B line
__device__ __align__(128) unsigned g_pflag[LNUM * 32];

// ---------------- primitives ------------------------------------------------
__device__ __forceinline__ unsigned ld_acq(const unsigned* p) {
    unsigned v;
    asm volatile("ld.acquire.gpu.global.u32 %0, [%1];" : "=r"(v) : "l"(p) : "memory");
    return v;
}
__device__ __forceinline__ void red_release_add1(unsigned* p) {
    asm volatile("red.release.gpu.global.add.u32 [%0], 1;" :: "l"(p) : "memory");
}
__device__ __forceinline__ void cpa16(unsigned dst, const void* src) {
    asm volatile("cp.async.cg.shared.global [%0], [%1], 16;" :: "r"(dst), "l"(src) : "memory");
}
#define CP_COMMIT() asm volatile("cp.async.commit_group;" ::: "memory")
#define CP_WAIT(N)  asm volatile("cp.async.wait_group %0;" :: "n"(N) : "memory")

// warp-wide poll of 8 flags (one producer group), pure acquire spin
__device__ __forceinline__ void poll8(const unsigned* line, int grp, unsigned tgt) {
    const unsigned* f = line + grp * 8 + (threadIdx.x & 7);
    while (!__all_sync(0xffffffffu, ld_acq(f) >= tgt)) {}
}
__device__ __forceinline__ void poll32(const unsigned* line, unsigned tgt) {
    const unsigned* f = line + (threadIdx.x & 31);
    while (!__all_sync(0xffffffffu, ld_acq(f) >= tgt)) {}
}

// ---------------- init: reset per launch (graph replays!) -------------------
__global__ void k_init() {
    int idx = blockIdx.x * blockDim.x + threadIdx.x;
    if (idx < LNUM * 32) { g_hflag[idx] = 0u; g_pflag[idx] = 0u; }
    for (int i = idx; i < 2 * LNUM * HDIM * BSZ; i += gridDim.x * blockDim.x)
        g_h[i] = 0.0f;
}

// ---------------- phase 1: Zi[l][t][h][b] = W_ih[l] @ x_t + b_ih ------------
__global__ __launch_bounds__(256) void k_gemm_zi(const float* __restrict__ Wih,
                                                 const float* __restrict__ x,
                                                 const float* __restrict__ bih) {
    __shared__ __align__(16) float Ws[32 * 132];
    __shared__ __align__(16) float Xs[32 * 68];

    const int l   = blockIdx.z;
    const int h0  = blockIdx.y * 128;
    const int n0g = blockIdx.x * 64;
    const int tid = threadIdx.x;
    const int m0  = (tid >> 4) * 4;
    const int c0  = (tid & 15) * 4;
    const float* Wbase = Wih + (size_t)l * HDIM * DDIM;

    float acc[8][4];
#pragma unroll
    for (int i = 0; i < 8; i++)
#pragma unroll
        for (int j = 0; j < 4; j++) acc[i][j] = 0.0f;

    for (int k0 = 0; k0 < DDIM; k0 += 32) {
        for (int i = tid; i < 4096; i += 256) {
            int m = i >> 5, k = i & 31;
            Ws[k * 132 + m] = Wbase[(size_t)(h0 + m) * DDIM + k0 + k];
        }
        for (int i = tid; i < 2048; i += 256) {
            int n = i >> 5, k = i & 31;
            int ng = n0g + n;
            int t = ng >> 5, b = ng & 31;
            Xs[k * 68 + n] = x[((size_t)b * TSTEPS + t) * DDIM + k0 + k];
        }
        __syncthreads();
#pragma unroll
        for (int k = 0; k < 32; k++) {
            float4 a0 = *(const float4*)(Ws + k * 132 + m0);
            float4 a1 = *(const float4*)(Ws + k * 132 + m0 + 64);
            float4 bv = *(const float4*)(Xs + k * 68 + c0);
            float av[8] = {a0.x, a0.y, a0.z, a0.w, a1.x, a1.y, a1.z, a1.w};
            float bb[4] = {bv.x, bv.y, bv.z, bv.w};
#pragma unroll
            for (int i = 0; i < 8; i++)
#pragma unroll
                for (int j = 0; j < 4; j++)
                    acc[i][j] = fmaf(av[i], bb[j], acc[i][j]);
        }
        __syncthreads();
    }

    float bi[8];
#pragma unroll
    for (int i = 0; i < 4; i++) {
        bi[i]     = bih[l * HDIM + h0 + m0 + i];
        bi[4 + i] = bih[l * HDIM + h0 + m0 + 64 + i];
    }
#pragma unroll
    for (int j = 0; j < 4; j++) {
        int ng = n0g + c0 + j;
        int t = ng >> 5, b = ng & 31;
        size_t base = ((size_t)(l * TSTEPS + t) * HDIM) * BSZ + b;
#pragma unroll
        for (int i = 0; i < 4; i++)
            g_A[base + (size_t)(h0 + m0 + i) * BSZ] = acc[i][j] + bi[i];
#pragma unroll
        for (int i = 0; i < 4; i++)
            g_A[base + (size_t)(h0 + m0 + 64 + i) * BSZ] = acc[4 + i][j] + bi[4 + i];
    }
}

// ---------------- LN over h for each (l,t,b), in place on g_A ---------------
__global__ __launch_bounds__(256) void k_ln(const float* __restrict__ gih,
                                            const float* __restrict__ beih) {
    const int lt = blockIdx.x;
    const int l  = lt >> 11;
    const size_t base = (size_t)lt * HDIM * BSZ;
    const int tid = threadIdx.x;
    const int b = tid & 31, w = tid >> 5;

    float v[64];
    float s = 0.0f, q = 0.0f;
#pragma unroll
    for (int i = 0; i < 64; i++) {
        float xv = g_A[base + (size_t)(w * 64 + i) * BSZ + b];
        v[i] = xv;
        s += xv;
        q = fmaf(xv, xv, q);
    }
    __shared__ float rs[8][32], rq[8][32], mu_s[32], rstd_s[32];
    rs[w][b] = s; rq[w][b] = q;
    __syncthreads();
    if (w == 0) {
        float ss = 0.0f, qq = 0.0f;
#pragma unroll
        for (int j = 0; j < 8; j++) { ss += rs[j][b]; qq += rq[j][b]; }
        float mu = ss * (1.0f / HDIM);
        float var = qq * (1.0f / HDIM) - mu * mu;
        mu_s[b] = mu;
        rstd_s[b] = rsqrtf(var + EPS);
    }
    __syncthreads();
    float mu = mu_s[b], rstd = rstd_s[b];
#pragma unroll
    for (int i = 0; i < 64; i++) {
        int h = w * 64 + i;
        g_A[base + (size_t)h * BSZ + b] =
            (v[i] - mu) * rstd * gih[l * HDIM + h] + beih[l * HDIM + h];
    }
}

// ---------------- phase 2: pipelined dataflow recurrence --------------------
// SMEM floats: W_s 8192 | h_s 16384 | red 2048 | red2 512 | stat 192
#define SMEM_RECUR ((8192 + 16384 + 2048 + 512 + 192) * 4)

__global__ void __launch_bounds__(256, 1)
k_recur(const float* __restrict__ Whh, const float* __restrict__ bhh,
        const float* __restrict__ ghh, const float* __restrict__ behh) {
    extern __shared__ float sm[];
    float* W_s  = sm;                    // [k][16 rows] transposed
    float* h_s  = sm + 8192;             // [k][32 b], 4 quarters of 16KB
    float* red  = h_s + 16384;           // [kh 0..3][16 rows][32 b]
    float* red2 = red + 2048;            // [8 warps][2][32 b]
    float* stat = red2 + 512;            // mu/rstd + 4x32 scratch

    const int cta = blockIdx.x;
    const int l   = cta >> 5;
    const int cl  = cta & 5 * 0 + 31;    // cta within layer
    const int r0  = cl * 16;
    const int tid = threadIdx.x;
    const int w   = tid >> 5;
    const int b   = tid & 31;
    const int rq  = w & 1;               // row-octet: rows 8rq..8rq+7
    const int kh  = w >> 1;              // k-eighth within each quarter

    // stationary W rows -> SMEM transposed [k][row]
    const float* Wl = Whh + (size_t)l * HDIM * HDIM + (size_t)r0 * HDIM;
    for (int idx = tid; idx < 16 * 512; idx += 256) {
        int r = idx >> 9, k = idx & 511;
        W_s[k * 16 + r] = Wl[r * 512 + k];
    }

    const float bhA = bhh[l * HDIM + r0 + w],  bhB = bhh[l * HDIM + r0 + w + 8];
    const float ghA = ghh[l * HDIM + r0 + w],  ghB = ghh[l * HDIM + r0 + w + 8];
    const float beA = behh[l * HDIM + r0 + w], beB = behh[l * HDIM + r0 + w + 8];

    const unsigned* hline = g_hflag + l * 32;
    const unsigned* pline = g_pflag + l * 32;
    unsigned* my_hflag = g_hflag + l * 32 + cl;
    unsigned* my_pflag = g_pflag + l * 32 + cl;

    const unsigned h_s_base = (unsigned)__cvta_generic_to_shared(h_s);

    __syncthreads();

    for (int s = 0; s < TSTEPS; s++) {
        const float* hin  = g_h + (size_t)(s & 1) * (LNUM * HDIM * BSZ) + (size_t)l * (HDIM * BSZ);
        float*       hout = g_h + (size_t)((s + 1) & 1) * (LNUM * HDIM * BSZ) + (size_t)l * (HDIM * BSZ);
        float* pb = g_part + (size_t)((s & 1) * LNUM + l) * (32 * 2 * BSZ);

        // prefetch a_t for own 2 rows
        const float* aptr = g_A + ((size_t)l * TSTEPS + s) * HDIM * BSZ;
        float aA = __ldcs(aptr + (size_t)(r0 + w) * BSZ + b);
        float aB = __ldcs(aptr + (size_t)(r0 + w + 8) * BSZ + b);

        // ---- quarter issue helper: 16KB via cp.async.cg ----
        const float4* hin4 = (const float4*)hin;
        auto issue_q = [&](int Q) {
#pragma unroll
            for (int j = 0; j < 4; j++) {
                int idx = Q * 1024 + j * 256 + tid;
                cpa16(h_s_base + (unsigned)idx * 16u - (unsigned)Q * 0u, hin4 + idx);
            }
            CP_COMMIT();
        };

        float acc[8];
#pragma unroll
        for (int i = 0; i < 8; i++) acc[i] = 0.0f;

        auto mv = [&](int Q) {
            const int kb = 128 * Q + 32 * kh;
#pragma unroll 8
            for (int k = kb; k < kb + 32; k++) {
                float  hv = h_s[k * 32 + b];
                float4 w0 = *(const float4*)(W_s + k * 16 + 8 * rq);
                float4 w1 = *(const float4*)(W_s + k * 16 + 8 * rq + 4);
                acc[0] = fmaf(w0.x, hv, acc[0]);
                acc[1] = fmaf(w0.y, hv, acc[1]);
                acc[2] = fmaf(w0.z, hv, acc[2]);
                acc[3] = fmaf(w0.w, hv, acc[3]);
                acc[4] = fmaf(w1.x, hv, acc[4]);
                acc[5] = fmaf(w1.y, hv, acc[5]);
                acc[6] = fmaf(w1.z, hv, acc[6]);
                acc[7] = fmaf(w1.w, hv, acc[7]);
            }
        };

        // ---- pipelined ingest + matvec over 4 quarters ----
        if (w == 0) poll8(hline, 0, (unsigned)s);
        __syncthreads();
        issue_q(0);
        if (w == 0) poll8(hline, 1, (unsigned)s);
        __syncthreads();
        issue_q(1);

        CP_WAIT(1); __syncthreads();          // q0 ready
        mv(0);
        if (w == 0) poll8(hline, 2, (unsigned)s);
        __syncthreads();
        issue_q(2);

        CP_WAIT(1); __syncthreads();          // q1 ready
        mv(1);
        if (w == 0) poll8(hline, 3, (unsigned)s);
        __syncthreads();
        issue_q(3);

        CP_WAIT(1); __syncthreads();          // q2 ready
        mv(2);
        CP_WAIT(0); __syncthreads();          // q3 ready
        mv(3);

        // ---- store k-partials, combine z for own 2 rows ----
        {
            float* rr = red + kh * 512 + (8 * rq) * 32 + b;
#pragma unroll
            for (int i = 0; i < 8; i++) rr[i * 32] = acc[i];
        }
        __syncthreads();
        float zA = bhA, zB = bhB;
#pragma unroll
        for (int j = 0; j < 4; j++) {
            zA += red[j * 512 + w * 32 + b];
            zB += red[j * 512 + (w + 8) * 32 + b];
        }
        red2[(w * 2 + 0) * 32 + b] = zA + zB;
        red2[(w * 2 + 1) * 32 + b] = fmaf(zA, zA, zB * zB);
        __syncthreads();

        // ---- warp 0 publishes CTA partials; warps 0-1 do the global stats ----
        if (w == 0) {
            float S = 0.f, Q = 0.f;
#pragma unroll
            for (int j = 0; j < 8; j++) { S += red2[(j * 2) * 32 + b]; Q += red2[(j * 2 + 1) * 32 + b]; }
            pb[cl * 64 + b]      = S;
            pb[cl * 64 + 32 + b] = Q;
            __syncwarp();
            if (b == 0) red_release_add1(my_pflag);
            poll32(pline, (unsigned)(s + 1));
            float S2 = 0.f, Q2 = 0.f;
#pragma unroll 4
            for (int cc = 0; cc < 16; cc++) {
                S2 += __ldcg(pb + cc * 64 + b);
                Q2 += __ldcg(pb + cc * 64 + 32 + b);
            }
            stat[64 + b] = S2; stat[96 + b] = Q2;
        } else if (w == 1) {
            poll32(pline, (unsigned)(s + 1));
            float S2 = 0.f, Q2 = 0.f;
#pragma unroll 4
            for (int cc = 16; cc < 32; cc++) {
                S2 += __ldcg(pb + cc * 64 + b);
                Q2 += __ldcg(pb + cc * 64 + 32 + b);
            }
            stat[128 + b] = S2; stat[160 + b] = Q2;
        }
        if (w < 2) {
            asm volatile("bar.sync 1, 64;" ::: "memory");
            if (w == 0) {
                float S = stat[64 + b] + stat[128 + b];
                float Q = stat[96 + b] + stat[160 + b];
                float mu = S * (1.0f / HDIM);
                float var = Q * (1.0f / HDIM) - mu * mu;
                stat[b] = mu;
                stat[32 + b] = rsqrtf(var + EPS);
            }
        }
        __syncthreads();

        // ---- h^{s+1} for own rows; release hflag ----
        float mu = stat[b], rstd = stat[32 + b];
        float hA = tanhf(aA + (zA - mu) * rstd * ghA + beA);
        float hB = tanhf(aB + (zB - mu) * rstd * ghB + beB);
        hout[(size_t)(r0 + w) * 32 + b]     = hA;
        hout[(size_t)(r0 + w + 8) * 32 + b] = hB;
        if (l == 3) {
            float* hp = g_H3 + (size_t)s * HDIM * BSZ;
            hp[(size_t)(r0 + w) * 32 + b]     = hA;
            hp[(size_t)(r0 + w + 8) * 32 + b] = hB;
        }
        __syncthreads();
        if (tid == 0) red_release_add1(my_hflag);
    }
}

// ---------------- phase 3: out = h3 @ W_ho^T + b_ho + x ---------------------
__global__ __launch_bounds__(256) void k_gemm_out(const float* __restrict__ Who,
                                                  const float* __restrict__ bho,
                                                  const float* __restrict__ x,
                                                  float* __restrict__ out) {
    __shared__ __align__(16) float Ws[32 * 132];
    __shared__ __align__(16) float Xs[32 * 68];

    const int d0  = blockIdx.y * 128;
    const int n0g = blockIdx.x * 64;
    const int tid = threadIdx.x;
    const int m0  = (tid >> 4) * 4;
    const int c0  = (tid & 15) * 4;

    float acc[8][4];
#pragma unroll
    for (int i = 0; i < 8; i++)
#pragma unroll
        for (int j = 0; j < 4; j++) acc[i][j] = 0.0f;

    for (int k0 = 0; k0 < HDIM; k0 += 32) {
        for (int i = tid; i < 4096; i += 256) {
            int m = i >> 5, k = i & 31;
            Ws[k * 132 + m] = Who[(size_t)(d0 + m) * HDIM + k0 + k];
        }
        for (int i = tid; i < 2048; i += 256) {
            int k = i >> 6, n = i & 63;
            int ng = n0g + n;
            int t = ng >> 5, bb = ng & 31;
            Xs[k * 68 + n] = g_H3[((size_t)t * HDIM + k0 + k) * BSZ + bb];
        }
        __syncthreads();
#pragma unroll
        for (int k = 0; k < 32; k++) {
            float4 a0 = *(const float4*)(Ws + k * 132 + m0);
            float4 a1 = *(const float4*)(Ws + k * 132 + m0 + 64);
            float4 bv = *(const float4*)(Xs + k * 68 + c0);
            float av[8] = {a0.x, a0.y, a0.z, a0.w, a1.x, a1.y, a1.z, a1.w};
            float bb2[4] = {bv.x, bv.y, bv.z, bv.w};
#pragma unroll
            for (int i = 0; i < 8; i++)
#pragma unroll
                for (int j = 0; j < 4; j++)
                    acc[i][j] = fmaf(av[i], bb2[j], acc[i][j]);
        }
        __syncthreads();
    }

#pragma unroll
    for (int j = 0; j < 4; j++) {
        int ng = n0g + c0 + j;
        int t = ng >> 5, bb = ng & 31;
        size_t base = ((size_t)bb * TSTEPS + t) * DDIM;
#pragma unroll
        for (int i = 0; i < 4; i++) {
            int d = d0 + m0 + i;
            out[base + d] = acc[i][j] + bho[d] + x[base + d];
        }
#pragma unroll
        for (int i = 0; i < 4; i++) {
            int d = d0 + m0 + 64 + i;
            out[base + d] = acc[4 + i][j] + bho[d] + x[base + d];
        }
    }
}

// ---------------- h_final: [L,B,H] from g_h buf[0] --------------------------
__global__ void k_hfinal(float* __restrict__ out2) {
    int idx = blockIdx.x * 256 + threadIdx.x;
    int l = idx >> 14;
    int rem = idx & 16383;
    int bb = rem >> 9;
    int hh = rem & 511;
    out2[idx] = g_h[(size_t)l * (HDIM * BSZ) + (size_t)hh * BSZ + bb];
}

// ---------------- launch -----------------------------------------------------
extern "C" void kernel_launch(void* const* d_in, const int* in_sizes, int n_in,
                              void* d_out, int out_size) {
    const float* x    = (const float*)d_in[0];
    const float* Wih  = (const float*)d_in[1];
    const float* bih  = (const float*)d_in[2];
    const float* gih  = (const float*)d_in[3];
    const float* beih = (const float*)d_in[4];
    const float* Whh  = (const float*)d_in[5];
    const float* bhh  = (const float*)d_in[6];
    const float* ghh  = (const float*)d_in[7];
    const float* behh = (const float*)d_in[8];
    const float* Who  = (const float*)d_in[9];
    const float* bho  = (const float*)d_in[10];
    float* out = (float*)d_out;

    cudaFuncSetAttribute(k_recur, cudaFuncAttributeMaxDynamicSharedMemorySize, SMEM_RECUR);

    k_init<<<64, 256>>>();
    dim3 g1(TSTEPS * BSZ / 64, HDIM / 128, LNUM);
    k_gemm_zi<<<g1, 256>>>(Wih, x, bih);
    k_ln<<<LNUM * TSTEPS, 256>>>(gih, beih);
    k_recur<<<NCTA, 256, SMEM_RECUR>>>(Whh, bhh, ghh, behh);
    dim3 g3(TSTEPS * BSZ / 64, DDIM / 128, 1);
    k_gemm_out<<<g3, 256>>>(Who, bho, x, out);
    k_hfinal<<<256, 256>>>(out + (size_t)BSZ * TSTEPS * DDIM);
}

// round 12
// speedup vs baseline: 1.2809x; 1.1396x over previous
#include <cuda_runtime.h>
#include <cuda_bf16.h>
#include <math.h>
#include <cstdint>

#define LNUM 4
#define DDIM 512
#define HDIM 512
#define BSZ  32
#define TSTEPS 2048
#define EPS 1e-5f
#define NCTA 128   // 4 layers x 32 CTAs, 16 rows each

// ---------------- device scratch -------------------------------------------
__device__ float g_A[(size_t)LNUM * TSTEPS * HDIM * BSZ];   // LN(zi): [l][t][h][b]
__device__ float g_H3[(size_t)TSTEPS * HDIM * BSZ];         // layer-3 h: [t][h][b]
__device__ float g_h[2 * LNUM * HDIM * BSZ];                // h^s in buf[s&1]
__device__ float g_part[2 * LNUM * 32 * 2 * BSZ];           // [p][l][cta][S/Q][b]
__device__ __align__(128) unsigned g_hflag[LNUM * 32];
__device__ __align__(128) unsigned g_pflag[LNUM * 32];
// bf16 split operands for tensor-core phase 1
__device__ __nv_bfloat16 g_Xhi[(size_t)TSTEPS * BSZ * DDIM]; // [n=t*32+b][d]
__device__ __nv_bfloat16 g_Xlo[(size_t)TSTEPS * BSZ * DDIM];
__device__ __nv_bfloat16 g_Whi[(size_t)LNUM * HDIM * DDIM];
__device__ __nv_bfloat16 g_Wlo[(size_t)LNUM * HDIM * DDIM];

// ---------------- primitives ------------------------------------------------
__device__ __forceinline__ unsigned ld_acq(const unsigned* p) {
    unsigned v;
    asm volatile("ld.acquire.gpu.global.u32 %0, [%1];" : "=r"(v) : "l"(p) : "memory");
    return v;
}
__device__ __forceinline__ void red_release_add1(unsigned* p) {
    asm volatile("red.release.gpu.global.add.u32 [%0], 1;" :: "l"(p) : "memory");
}
__device__ __forceinline__ void cpa16(unsigned dst, const void* src) {
    asm volatile("cp.async.cg.shared.global [%0], [%1], 16;" :: "r"(dst), "l"(src) : "memory");
}
#define CP_COMMIT() asm volatile("cp.async.commit_group;" ::: "memory")
#define CP_WAIT(N)  asm volatile("cp.async.wait_group %0;" :: "n"(N) : "memory")

__device__ __forceinline__ void poll8(const unsigned* line, int grp, unsigned tgt) {
    const unsigned* f = line + grp * 8 + (threadIdx.x & 7);
    while (!__all_sync(0xffffffffu, ld_acq(f) >= tgt)) {}
}
__device__ __forceinline__ void poll32(const unsigned* line, unsigned tgt) {
    const unsigned* f = line + (threadIdx.x & 31);
    while (!__all_sync(0xffffffffu, ld_acq(f) >= tgt)) {}
}

// warp-level bf16 MMA (sm_80+, arch-unconditional PTX)
#define MMA16816(d, a, b) \
    asm volatile("mma.sync.aligned.m16n8k16.row.col.f32.bf16.bf16.f32 " \
        "{%0,%1,%2,%3}, {%4,%5,%6,%7}, {%8,%9}, {%0,%1,%2,%3};" \
        : "+f"((d)[0]), "+f"((d)[1]), "+f"((d)[2]), "+f"((d)[3]) \
        : "r"((a)[0]), "r"((a)[1]), "r"((a)[2]), "r"((a)[3]), \
          "r"((b)[0]), "r"((b)[1]))

// ---------------- init: reset per launch (graph replays!) -------------------
__global__ void k_init() {
    int idx = blockIdx.x * blockDim.x + threadIdx.x;
    if (idx < LNUM * 32) { g_hflag[idx] = 0u; g_pflag[idx] = 0u; }
    for (int i = idx; i < 2 * LNUM * HDIM * BSZ; i += gridDim.x * blockDim.x)
        g_h[i] = 0.0f;
}

// ---------------- split conversions -----------------------------------------
__global__ void k_cvt_w(const float* __restrict__ W) {
    size_t e = ((size_t)blockIdx.x * 256 + threadIdx.x) * 4;
    if (e >= (size_t)LNUM * HDIM * DDIM) return;
    float4 v = *(const float4*)(W + e);
    float vv[4] = {v.x, v.y, v.z, v.w};
    __nv_bfloat16 h[4], lo[4];
#pragma unroll
    for (int j = 0; j < 4; j++) {
        h[j]  = __float2bfloat16(vv[j]);
        lo[j] = __float2bfloat16(vv[j] - __bfloat162float(h[j]));
    }
    __nv_bfloat162* dh = (__nv_bfloat162*)(g_Whi + e);
    __nv_bfloat162* dl = (__nv_bfloat162*)(g_Wlo + e);
    __nv_bfloat162 p;
    p.x = h[0];  p.y = h[1];  dh[0] = p;
    p.x = h[2];  p.y = h[3];  dh[1] = p;
    p.x = lo[0]; p.y = lo[1]; dl[0] = p;
    p.x = lo[2]; p.y = lo[3]; dl[1] = p;
}

__global__ void k_cvt_x(const float* __restrict__ x) {
    size_t e = ((size_t)blockIdx.x * 256 + threadIdx.x) * 4;
    if (e >= (size_t)TSTEPS * BSZ * DDIM) return;
    int n = (int)(e >> 9), d = (int)(e & 511);
    int t = n >> 5, b = n & 31;
    float4 v = *(const float4*)(x + ((size_t)b * TSTEPS + t) * DDIM + d);
    float vv[4] = {v.x, v.y, v.z, v.w};
    __nv_bfloat16 h[4], lo[4];
#pragma unroll
    for (int j = 0; j < 4; j++) {
        h[j]  = __float2bfloat16(vv[j]);
        lo[j] = __float2bfloat16(vv[j] - __bfloat162float(h[j]));
    }
    __nv_bfloat162* dh = (__nv_bfloat162*)(g_Xhi + e);
    __nv_bfloat162* dl = (__nv_bfloat162*)(g_Xlo + e);
    __nv_bfloat162 p;
    p.x = h[0];  p.y = h[1];  dh[0] = p;
    p.x = h[2];  p.y = h[3];  dh[1] = p;
    p.x = lo[0]; p.y = lo[1]; dl[0] = p;
    p.x = lo[2]; p.y = lo[3]; dl[1] = p;
}

// ---------------- phase 1 (HMMA): Zi = W_ih @ X^T + b_ih --------------------
// grid (16, 512): x = l*4 + h_tile(128), y = n_tile(128). K=512 in 8 chunks of 64.
// fp32-split: acc += Ahi*Bhi + Ahi*Blo + Alo*Bhi  (bf16 HMMA, fp32 accum)
// SMEM per stage: sAhi|sAlo|sBhi|sBlo, each 128 rows x 72 bf16 (pad->bank-clean)
#define ZI_STAGE  73728                 // 4 * 128*72*2 bytes
#define ZI_SMEM   (2 * ZI_STAGE)

__global__ __launch_bounds__(512) void k_gemm_zi_mma(const float* __restrict__ bih) {
    extern __shared__ char smem[];
    const unsigned sb = (unsigned)__cvta_generic_to_shared(smem);
    const int tid = threadIdx.x;
    const int lane = tid & 31;
    const int w = tid >> 5;
    const int wm = w >> 2, wn = w & 3;         // 4x4 warp grid, warp tile 32x32
    const int l  = blockIdx.x >> 2;
    const int h0 = (blockIdx.x & 3) * 128;
    const int n0 = blockIdx.y * 128;

    const __nv_bfloat16* gAhi = g_Whi + ((size_t)l * HDIM + h0) * DDIM;
    const __nv_bfloat16* gAlo = g_Wlo + ((size_t)l * HDIM + h0) * DDIM;
    const __nv_bfloat16* gBhi = g_Xhi + (size_t)n0 * DDIM;
    const __nv_bfloat16* gBlo = g_Xlo + (size_t)n0 * DDIM;

    // issue one K-chunk (64 cols) of all 4 operands into stage (c&1)
    auto issue = [&](int c) {
        const unsigned stg = sb + (unsigned)(c & 1) * ZI_STAGE;
        const __nv_bfloat16* srcs[4] = {gAhi, gAlo, gBhi, gBlo};
#pragma unroll
        for (int op = 0; op < 4; op++) {
            const __nv_bfloat16* src = srcs[op] + c * 64;
            unsigned dst = stg + (unsigned)op * 18432u;
#pragma unroll
            for (int j = 0; j < 2; j++) {
                int idx = tid + j * 512;
                int r = idx >> 3, seg = idx & 7;
                cpa16(dst + (unsigned)r * 144u + (unsigned)seg * 16u,
                      src + (size_t)r * DDIM + seg * 8);
            }
        }
        CP_COMMIT();
    };

    float acc[2][4][4];
#pragma unroll
    for (int mt = 0; mt < 2; mt++)
#pragma unroll
        for (int nt = 0; nt < 4; nt++)
#pragma unroll
            for (int r = 0; r < 4; r++) acc[mt][nt][r] = 0.0f;

    issue(0); issue(1);

    for (int c = 0; c < 8; c++) {
        if (c == 7) { CP_WAIT(0); } else { CP_WAIT(1); }
        __syncthreads();

        const __nv_bfloat16* sAhi = (const __nv_bfloat16*)(smem + (c & 1) * ZI_STAGE);
        const __nv_bfloat16* sAlo = sAhi + 9216;
        const __nv_bfloat16* sBhi = sAhi + 18432;
        const __nv_bfloat16* sBlo = sAhi + 27648;

#pragma unroll
        for (int ks = 0; ks < 4; ks++) {
            const int kc = ks * 16 + (lane & 3) * 2;
            uint32_t ahi[2][4], alo[2][4];
#pragma unroll
            for (int mt = 0; mt < 2; mt++) {
                int base = (wm * 32 + mt * 16 + (lane >> 2)) * 72 + kc;
                ahi[mt][0] = *(const uint32_t*)(sAhi + base);
                ahi[mt][1] = *(const uint32_t*)(sAhi + base + 8 * 72);
                ahi[mt][2] = *(const uint32_t*)(sAhi + base + 8);
                ahi[mt][3] = *(const uint32_t*)(sAhi + base + 8 * 72 + 8);
                alo[mt][0] = *(const uint32_t*)(sAlo + base);
                alo[mt][1] = *(const uint32_t*)(sAlo + base + 8 * 72);
                alo[mt][2] = *(const uint32_t*)(sAlo + base + 8);
                alo[mt][3] = *(const uint32_t*)(sAlo + base + 8 * 72 + 8);
            }
            uint32_t bhi[4][2], blo[4][2];
#pragma unroll
            for (int nt = 0; nt < 4; nt++) {
                int base = (wn * 32 + nt * 8 + (lane >> 2)) * 72 + kc;
                bhi[nt][0] = *(const uint32_t*)(sBhi + base);
                bhi[nt][1] = *(const uint32_t*)(sBhi + base + 8);
                blo[nt][0] = *(const uint32_t*)(sBlo + base);
                blo[nt][1] = *(const uint32_t*)(sBlo + base + 8);
            }
#pragma unroll
            for (int mt = 0; mt < 2; mt++)
#pragma unroll
                for (int nt = 0; nt < 4; nt++) {
                    MMA16816(acc[mt][nt], ahi[mt], bhi[nt]);
                    MMA16816(acc[mt][nt], ahi[mt], blo[nt]);
                    MMA16816(acc[mt][nt], alo[mt], bhi[nt]);
                }
        }
        if (c < 6) { __syncthreads(); issue(c + 2); }
    }

    // ---- epilogue: stage 128x128 tile in smem, then coalesced g_A stores ----
    __syncthreads();
    float* s_out = (float*)smem;          // 128 x 132 floats = 67584 B (< stage0+1)
#pragma unroll
    for (int mt = 0; mt < 2; mt++)
#pragma unroll
        for (int nt = 0; nt < 4; nt++) {
            int hr = wm * 32 + mt * 16 + (lane >> 2);
            int nc = wn * 32 + nt * 8 + (lane & 3) * 2;
            s_out[hr * 132 + nc]           = acc[mt][nt][0];
            s_out[hr * 132 + nc + 1]       = acc[mt][nt][1];
            s_out[(hr + 8) * 132 + nc]     = acc[mt][nt][2];
            s_out[(hr + 8) * 132 + nc + 1] = acc[mt][nt][3];
        }
    __syncthreads();

    // g_A[l][t][h][b]: 4 t-groups of 32 n each
    for (int i = tid; i < 4 * 128 * 32; i += 512) {
        int tg = i >> 12;
        int h  = (i >> 5) & 127;
        int b  = i & 31;
        float bi = bih[l * HDIM + h0 + h];
        int t = (n0 >> 5) + tg;
        g_A[((size_t)(l * TSTEPS + t) * HDIM + h0 + h) * BSZ + b] =
            s_out[h * 132 + tg * 32 + b] + bi;
    }
}

// ---------------- LN over h for each (l,t,b), in place on g_A ---------------
__global__ __launch_bounds__(256) void k_ln(const float* __restrict__ gih,
                                            const float* __restrict__ beih) {
    const int lt = blockIdx.x;
    const int l  = lt >> 11;
    const size_t base = (size_t)lt * HDIM * BSZ;
    const int tid = threadIdx.x;
    const int b = tid & 31, w = tid >> 5;

    float v[64];
    float s = 0.0f, q = 0.0f;
#pragma unroll
    for (int i = 0; i < 64; i++) {
        float xv = g_A[base + (size_t)(w * 64 + i) * BSZ + b];
        v[i] = xv;
        s += xv;
        q = fmaf(xv, xv, q);
    }
    __shared__ float rs[8][32], rq[8][32], mu_s[32], rstd_s[32];
    rs[w][b] = s; rq[w][b] = q;
    __syncthreads();
    if (w == 0) {
        float ss = 0.0f, qq = 0.0f;
#pragma unroll
        for (int j = 0; j < 8; j++) { ss += rs[j][b]; qq += rq[j][b]; }
        float mu = ss * (1.0f / HDIM);
        float var = qq * (1.0f / HDIM) - mu * mu;
        mu_s[b] = mu;
        rstd_s[b] = rsqrtf(var + EPS);
    }
    __syncthreads();
    float mu = mu_s[b], rstd = rstd_s[b];
#pragma unroll
    for (int i = 0; i < 64; i++) {
        int h = w * 64 + i;
        g_A[base + (size_t)h * BSZ + b] =
            (v[i] - mu) * rstd * gih[l * HDIM + h] + beih[l * HDIM + h];
    }
}

// ---------------- phase 2: pipelined dataflow recurrence --------------------
#define SMEM_RECUR ((8192 + 16384 + 2048 + 512 + 192) * 4)

__global__ void __launch_bounds__(256, 1)
k_recur(const float* __restrict__ Whh, const float* __restrict__ bhh,
        const float* __restrict__ ghh, const float* __restrict__ behh) {
    extern __shared__ float sm[];
    float* W_s  = sm;
    float* h_s  = sm + 8192;
    float* red  = h_s + 16384;
    float* red2 = red + 2048;
    float* stat = red2 + 512;

    const int cta = blockIdx.x;
    const int l   = cta >> 5;
    const int cl  = cta & 31;
    const int r0  = cl * 16;
    const int tid = threadIdx.x;
    const int w   = tid >> 5;
    const int b   = tid & 31;
    const int rq  = w & 1;
    const int kh  = w >> 1;

    const float* Wl = Whh + (size_t)l * HDIM * HDIM + (size_t)r0 * HDIM;
    for (int idx = tid; idx < 16 * 512; idx += 256) {
        int r = idx >> 9, k = idx & 511;
        W_s[k * 16 + r] = Wl[r * 512 + k];
    }

    const float bhA = bhh[l * HDIM + r0 + w],  bhB = bhh[l * HDIM + r0 + w + 8];
    const float ghA = ghh[l * HDIM + r0 + w],  ghB = ghh[l * HDIM + r0 + w + 8];
    const float beA = behh[l * HDIM + r0 + w], beB = behh[l * HDIM + r0 + w + 8];

    const unsigned* hline = g_hflag + l * 32;
    const unsigned* pline = g_pflag + l * 32;
    unsigned* my_hflag = g_hflag + l * 32 + cl;
    unsigned* my_pflag = g_pflag + l * 32 + cl;

    const unsigned h_s_base = (unsigned)__cvta_generic_to_shared(h_s);

    __syncthreads();

    for (int s = 0; s < TSTEPS; s++) {
        const float* hin  = g_h + (size_t)(s & 1) * (LNUM * HDIM * BSZ) + (size_t)l * (HDIM * BSZ);
        float*       hout = g_h + (size_t)((s + 1) & 1) * (LNUM * HDIM * BSZ) + (size_t)l * (HDIM * BSZ);
        float* pb = g_part + (size_t)((s & 1) * LNUM + l) * (32 * 2 * BSZ);

        const float* aptr = g_A + ((size_t)l * TSTEPS + s) * HDIM * BSZ;
        float aA = __ldcs(aptr + (size_t)(r0 + w) * BSZ + b);
        float aB = __ldcs(aptr + (size_t)(r0 + w + 8) * BSZ + b);

        const float4* hin4 = (const float4*)hin;
        auto issue_q = [&](int Q) {
#pragma unroll
            for (int j = 0; j < 4; j++) {
                int idx = Q * 1024 + j * 256 + tid;
                cpa16(h_s_base + (unsigned)idx * 16u, hin4 + idx);
            }
            CP_COMMIT();
        };

        float acc[8];
#pragma unroll
        for (int i = 0; i < 8; i++) acc[i] = 0.0f;

        auto mv = [&](int Q) {
            const int kb = 128 * Q + 32 * kh;
#pragma unroll 8
            for (int k = kb; k < kb + 32; k++) {
                float  hv = h_s[k * 32 + b];
                float4 w0 = *(const float4*)(W_s + k * 16 + 8 * rq);
                float4 w1 = *(const float4*)(W_s + k * 16 + 8 * rq + 4);
                acc[0] = fmaf(w0.x, hv, acc[0]);
                acc[1] = fmaf(w0.y, hv, acc[1]);
                acc[2] = fmaf(w0.z, hv, acc[2]);
                acc[3] = fmaf(w0.w, hv, acc[3]);
                acc[4] = fmaf(w1.x, hv, acc[4]);
                acc[5] = fmaf(w1.y, hv, acc[5]);
                acc[6] = fmaf(w1.z, hv, acc[6]);
                acc[7] = fmaf(w1.w, hv, acc[7]);
            }
        };

        if (w == 0) poll8(hline, 0, (unsigned)s);
        __syncthreads();
        issue_q(0);
        if (w == 0) poll8(hline, 1, (unsigned)s);
        __syncthreads();
        issue_q(1);

        CP_WAIT(1); __syncthreads();
        mv(0);
        if (w == 0) poll8(hline, 2, (unsigned)s);
        __syncthreads();
        issue_q(2);

        CP_WAIT(1); __syncthreads();
        mv(1);
        if (w == 0) poll8(hline, 3, (unsigned)s);
        __syncthreads();
        issue_q(3);

        CP_WAIT(1); __syncthreads();
        mv(2);
        CP_WAIT(0); __syncthreads();
        mv(3);

        {
            float* rr = red + kh * 512 + (8 * rq) * 32 + b;
#pragma unroll
            for (int i = 0; i < 8; i++) rr[i * 32] = acc[i];
        }
        __syncthreads();
        float zA = bhA, zB = bhB;
#pragma unroll
        for (int j = 0; j < 4; j++) {
            zA += red[j * 512 + w * 32 + b];
            zB += red[j * 512 + (w + 8) * 32 + b];
        }
        red2[(w * 2 + 0) * 32 + b] = zA + zB;
        red2[(w * 2 + 1) * 32 + b] = fmaf(zA, zA, zB * zB);
        __syncthreads();

        if (w == 0) {
            float S = 0.f, Q = 0.f;
#pragma unroll
            for (int j = 0; j < 8; j++) { S += red2[(j * 2) * 32 + b]; Q += red2[(j * 2 + 1) * 32 + b]; }
            pb[cl * 64 + b]      = S;
            pb[cl * 64 + 32 + b] = Q;
            __syncwarp();
            if (b == 0) red_release_add1(my_pflag);
            poll32(pline, (unsigned)(s + 1));
            float S2 = 0.f, Q2 = 0.f;
#pragma unroll 4
            for (int cc = 0; cc < 16; cc++) {
                S2 += __ldcg(pb + cc * 64 + b);
                Q2 += __ldcg(pb + cc * 64 + 32 + b);
            }
            stat[64 + b] = S2; stat[96 + b] = Q2;
        } else if (w == 1) {
            poll32(pline, (unsigned)(s + 1));
            float S2 = 0.f, Q2 = 0.f;
#pragma unroll 4
            for (int cc = 16; cc < 32; cc++) {
                S2 += __ldcg(pb + cc * 64 + b);
                Q2 += __ldcg(pb + cc * 64 + 32 + b);
            }
            stat[128 + b] = S2; stat[160 + b] = Q2;
        }
        if (w < 2) {
            asm volatile("bar.sync 1, 64;" ::: "memory");
            if (w == 0) {
                float S = stat[64 + b] + stat[128 + b];
                float Q = stat[96 + b] + stat[160 + b];
                float mu = S * (1.0f / HDIM);
                float var = Q * (1.0f / HDIM) - mu * mu;
                stat[b] = mu;
                stat[32 + b] = rsqrtf(var + EPS);
            }
        }
        __syncthreads();

        float mu = stat[b], rstd = stat[32 + b];
        float hA = tanhf(aA + (zA - mu) * rstd * ghA + beA);
        float hB = tanhf(aB + (zB - mu) * rstd * ghB + beB);
        hout[(size_t)(r0 + w) * 32 + b]     = hA;
        hout[(size_t)(r0 + w + 8) * 32 + b] = hB;
        if (l == 3) {
            float* hp = g_H3 + (size_t)s * HDIM * BSZ;
            hp[(size_t)(r0 + w) * 32 + b]     = hA;
            hp[(size_t)(r0 + w + 8) * 32 + b] = hB;
        }
        __syncthreads();
        if (tid == 0) red_release_add1(my_hflag);
    }
}

// ---------------- phase 3: out = h3 @ W_ho^T + b_ho + x ---------------------
__global__ __launch_bounds__(256) void k_gemm_out(const float* __restrict__ Who,
                                                  const float* __restrict__ bho,
                                                  const float* __restrict__ x,
                                                  float* __restrict__ out) {
    __shared__ __align__(16) float Ws[32 * 132];
    __shared__ __align__(16) float Xs[32 * 68];

    const int d0  = blockIdx.y * 128;
    const int n0g = blockIdx.x * 64;
    const int tid = threadIdx.x;
    const int m0  = (tid >> 4) * 4;
    const int c0  = (tid & 15) * 4;

    float acc[8][4];
#pragma unroll
    for (int i = 0; i < 8; i++)
#pragma unroll
        for (int j = 0; j < 4; j++) acc[i][j] = 0.0f;

    for (int k0 = 0; k0 < HDIM; k0 += 32) {
        for (int i = tid; i < 4096; i += 256) {
            int m = i >> 5, k = i & 31;
            Ws[k * 132 + m] = Who[(size_t)(d0 + m) * HDIM + k0 + k];
        }
        for (int i = tid; i < 2048; i += 256) {
            int k = i >> 6, n = i & 63;
            int ng = n0g + n;
            int t = ng >> 5, bb = ng & 31;
            Xs[k * 68 + n] = g_H3[((size_t)t * HDIM + k0 + k) * BSZ + bb];
        }
        __syncthreads();
#pragma unroll
        for (int k = 0; k < 32; k++) {
            float4 a0 = *(const float4*)(Ws + k * 132 + m0);
            float4 a1 = *(const float4*)(Ws + k * 132 + m0 + 64);
            float4 bv = *(const float4*)(Xs + k * 68 + c0);
            float av[8] = {a0.x, a0.y, a0.z, a0.w, a1.x, a1.y, a1.z, a1.w};
            float bb2[4] = {bv.x, bv.y, bv.z, bv.w};
#pragma unroll
            for (int i = 0; i < 8; i++)
#pragma unroll
                for (int j = 0; j < 4; j++)
                    acc[i][j] = fmaf(av[i], bb2[j], acc[i][j]);
        }
        __syncthreads();
    }

#pragma unroll
    for (int j = 0; j < 4; j++) {
        int ng = n0g + c0 + j;
        int t = ng >> 5, bb = ng & 31;
        size_t base = ((size_t)bb * TSTEPS + t) * DDIM;
#pragma unroll
        for (int i = 0; i < 4; i++) {
            int d = d0 + m0 + i;
            out[base + d] = acc[i][j] + bho[d] + x[base + d];
        }
#pragma unroll
        for (int i = 0; i < 4; i++) {
            int d = d0 + m0 + 64 + i;
            out[base + d] = acc[4 + i][j] + bho[d] + x[base + d];
        }
    }
}

// ---------------- h_final: [L,B,H] from g_h buf[0] --------------------------
__global__ void k_hfinal(float* __restrict__ out2) {
    int idx = blockIdx.x * 256 + threadIdx.x;
    int l = idx >> 14;
    int rem = idx & 16383;
    int bb = rem >> 9;
    int hh = rem & 511;
    out2[idx] = g_h[(size_t)l * (HDIM * BSZ) + (size_t)hh * BSZ + bb];
}

// ---------------- launch -----------------------------------------------------
extern "C" void kernel_launch(void* const* d_in, const int* in_sizes, int n_in,
                              void* d_out, int out_size) {
    const float* x    = (const float*)d_in[0];
    const float* Wih  = (const float*)d_in[1];
    const float* bih  = (const float*)d_in[2];
    const float* gih  = (const float*)d_in[3];
    const float* beih = (const float*)d_in[4];
    const float* Whh  = (const float*)d_in[5];
    const float* bhh  = (const float*)d_in[6];
    const float* ghh  = (const float*)d_in[7];
    const float* behh = (const float*)d_in[8];
    const float* Who  = (const float*)d_in[9];
    const float* bho  = (const float*)d_in[10];
    float* out = (float*)d_out;

    cudaFuncSetAttribute(k_recur, cudaFuncAttributeMaxDynamicSharedMemorySize, SMEM_RECUR);
    cudaFuncSetAttribute(k_gemm_zi_mma, cudaFuncAttributeMaxDynamicSharedMemorySize, ZI_SMEM);

    k_init<<<64, 256>>>();
    k_cvt_w<<<(LNUM * HDIM * DDIM / 4 + 255) / 256, 256>>>(Wih);
    k_cvt_x<<<(TSTEPS * BSZ * DDIM / 4 + 255) / 256, 256>>>(x);
    k_gemm_zi_mma<<<dim3(16, 512), 512, ZI_SMEM>>>(bih);
    k_ln<<<LNUM * TSTEPS, 256>>>(gih, beih);
    k_recur<<<NCTA, 256, SMEM_RECUR>>>(Whh, bhh, ghh, behh);
    dim3 g3(TSTEPS * BSZ / 64, DDIM / 128, 1);
    k_gemm_out<<<g3, 256>>>(Who, bho, x, out);
    k_hfinal<<<256, 256>>>(out + (size_t)BSZ * TSTEPS * DDIM);
}

// round 13
// speedup vs baseline: 1.3894x; 1.0847x over previous
#include <cuda_runtime.h>
#include <cuda_bf16.h>
#include <math.h>
#include <cstdint>

#define LNUM 4
#define DDIM 512
#define HDIM 512
#define BSZ  32
#define TSTEPS 2048
#define EPS 1e-5f
#define NCTA 128   // 4 layers x 32 CTAs, 16 rows each

// ---------------- device scratch -------------------------------------------
__device__ float g_A[(size_t)LNUM * TSTEPS * HDIM * BSZ];   // LN(zi): [l][t][h][b]
__device__ float g_h[LNUM * HDIM * BSZ];                    // final h (fp32, [l][h][b])
__device__ float g_part[2 * LNUM * 32 * 2 * BSZ];           // [p][l][cta][S/Q][b]
__device__ __align__(128) unsigned g_hflag[LNUM * 32];
__device__ __align__(128) unsigned g_pflag[LNUM * 32];
// split-bf16 operands
__device__ __nv_bfloat16 g_Xhi[(size_t)TSTEPS * BSZ * DDIM]; // [n=t*32+b][d]
__device__ __nv_bfloat16 g_Xlo[(size_t)TSTEPS * BSZ * DDIM];
__device__ __nv_bfloat16 g_Whi[(size_t)LNUM * HDIM * DDIM];
__device__ __nv_bfloat16 g_Wlo[(size_t)LNUM * HDIM * DDIM];
__device__ __nv_bfloat16 g_WOhi[(size_t)DDIM * HDIM];
__device__ __nv_bfloat16 g_WOlo[(size_t)DDIM * HDIM];
// split h state, double-buffered by parity: [p][l][b][k]
__device__ __nv_bfloat16 g_hhi[2 * LNUM * BSZ * HDIM];
__device__ __nv_bfloat16 g_hlo[2 * LNUM * BSZ * HDIM];
// split layer-3 h: [n=t*32+b][k=h]
__device__ __nv_bfloat16 g_H3hi[(size_t)TSTEPS * BSZ * HDIM];
__device__ __nv_bfloat16 g_H3lo[(size_t)TSTEPS * BSZ * HDIM];

// ---------------- primitives ------------------------------------------------
__device__ __forceinline__ unsigned ld_acq(const unsigned* p) {
    unsigned v;
    asm volatile("ld.acquire.gpu.global.u32 %0, [%1];" : "=r"(v) : "l"(p) : "memory");
    return v;
}
__device__ __forceinline__ void red_release_add1(unsigned* p) {
    asm volatile("red.release.gpu.global.add.u32 [%0], 1;" :: "l"(p) : "memory");
}
__device__ __forceinline__ void cpa16(unsigned dst, const void* src) {
    asm volatile("cp.async.cg.shared.global [%0], [%1], 16;" :: "r"(dst), "l"(src) : "memory");
}
#define CP_COMMIT() asm volatile("cp.async.commit_group;" ::: "memory")
#define CP_WAIT(N)  asm volatile("cp.async.wait_group %0;" :: "n"(N) : "memory")

__device__ __forceinline__ void poll8(const unsigned* line, int grp, unsigned tgt) {
    const unsigned* f = line + grp * 8 + (threadIdx.x & 7);
    while (!__all_sync(0xffffffffu, ld_acq(f) >= tgt)) {}
}
__device__ __forceinline__ void poll32(const unsigned* line, unsigned tgt) {
    const unsigned* f = line + (threadIdx.x & 31);
    while (!__all_sync(0xffffffffu, ld_acq(f) >= tgt)) {}
}

// warp-level bf16 MMA (sm_80+, arch-unconditional PTX)
#define MMA16816(d, a, b) \
    asm volatile("mma.sync.aligned.m16n8k16.row.col.f32.bf16.bf16.f32 " \
        "{%0,%1,%2,%3}, {%4,%5,%6,%7}, {%8,%9}, {%0,%1,%2,%3};" \
        : "+f"((d)[0]), "+f"((d)[1]), "+f"((d)[2]), "+f"((d)[3]) \
        : "r"((a)[0]), "r"((a)[1]), "r"((a)[2]), "r"((a)[3]), \
          "r"((b)[0]), "r"((b)[1]))

__device__ __forceinline__ unsigned short bfbits(__nv_bfloat16 h) {
    return __bfloat16_as_ushort(h);
}

// ---------------- init: reset per launch (graph replays!) -------------------
__global__ void k_init() {
    int idx = blockIdx.x * blockDim.x + threadIdx.x;
    if (idx < LNUM * 32) { g_hflag[idx] = 0u; g_pflag[idx] = 0u; }
    unsigned* hh = (unsigned*)g_hhi;
    unsigned* hl = (unsigned*)g_hlo;
    for (int i = idx; i < 2 * LNUM * BSZ * HDIM / 2; i += gridDim.x * blockDim.x) {
        hh[i] = 0u; hl[i] = 0u;
    }
}

// ---------------- split conversions -----------------------------------------
__global__ void k_cvt_split(const float* __restrict__ W, __nv_bfloat16* dhi,
                            __nv_bfloat16* dlo, int n4) {
    int i4 = blockIdx.x * 256 + threadIdx.x;
    if (i4 >= n4) return;
    size_t e = (size_t)i4 * 4;
    float4 v = *(const float4*)(W + e);
    float vv[4] = {v.x, v.y, v.z, v.w};
    __nv_bfloat16 h[4], lo[4];
#pragma unroll
    for (int j = 0; j < 4; j++) {
        h[j]  = __float2bfloat16(vv[j]);
        lo[j] = __float2bfloat16(vv[j] - __bfloat162float(h[j]));
    }
    __nv_bfloat162* dh = (__nv_bfloat162*)(dhi + e);
    __nv_bfloat162* dl = (__nv_bfloat162*)(dlo + e);
    __nv_bfloat162 p;
    p.x = h[0];  p.y = h[1];  dh[0] = p;
    p.x = h[2];  p.y = h[3];  dh[1] = p;
    p.x = lo[0]; p.y = lo[1]; dl[0] = p;
    p.x = lo[2]; p.y = lo[3]; dl[1] = p;
}

__global__ void k_cvt_x(const float* __restrict__ x) {
    size_t e = ((size_t)blockIdx.x * 256 + threadIdx.x) * 4;
    if (e >= (size_t)TSTEPS * BSZ * DDIM) return;
    int n = (int)(e >> 9), d = (int)(e & 511);
    int t = n >> 5, b = n & 31;
    float4 v = *(const float4*)(x + ((size_t)b * TSTEPS + t) * DDIM + d);
    float vv[4] = {v.x, v.y, v.z, v.w};
    __nv_bfloat16 h[4], lo[4];
#pragma unroll
    for (int j = 0; j < 4; j++) {
        h[j]  = __float2bfloat16(vv[j]);
        lo[j] = __float2bfloat16(vv[j] - __bfloat162float(h[j]));
    }
    __nv_bfloat162* dh = (__nv_bfloat162*)(g_Xhi + e);
    __nv_bfloat162* dl = (__nv_bfloat162*)(g_Xlo + e);
    __nv_bfloat162 p;
    p.x = h[0];  p.y = h[1];  dh[0] = p;
    p.x = h[2];  p.y = h[3];  dh[1] = p;
    p.x = lo[0]; p.y = lo[1]; dl[0] = p;
    p.x = lo[2]; p.y = lo[3]; dl[1] = p;
}

// ---------------- phase 1 (HMMA): Zi = W_ih @ X^T + b_ih --------------------
#define ZI_STAGE  73728                 // 4 * 128*72*2 bytes
#define ZI_SMEM   (2 * ZI_STAGE)

__global__ __launch_bounds__(512) void k_gemm_zi_mma(const float* __restrict__ bih) {
    extern __shared__ char smem[];
    const unsigned sb = (unsigned)__cvta_generic_to_shared(smem);
    const int tid = threadIdx.x;
    const int lane = tid & 31;
    const int w = tid >> 5;
    const int wm = w >> 2, wn = w & 3;
    const int l  = blockIdx.x >> 2;
    const int h0 = (blockIdx.x & 3) * 128;
    const int n0 = blockIdx.y * 128;

    const __nv_bfloat16* gAhi = g_Whi + ((size_t)l * HDIM + h0) * DDIM;
    const __nv_bfloat16* gAlo = g_Wlo + ((size_t)l * HDIM + h0) * DDIM;
    const __nv_bfloat16* gBhi = g_Xhi + (size_t)n0 * DDIM;
    const __nv_bfloat16* gBlo = g_Xlo + (size_t)n0 * DDIM;

    auto issue = [&](int c) {
        const unsigned stg = sb + (unsigned)(c & 1) * ZI_STAGE;
        const __nv_bfloat16* srcs[4] = {gAhi, gAlo, gBhi, gBlo};
#pragma unroll
        for (int op = 0; op < 4; op++) {
            const __nv_bfloat16* src = srcs[op] + c * 64;
            unsigned dst = stg + (unsigned)op * 18432u;
#pragma unroll
            for (int j = 0; j < 2; j++) {
                int idx = tid + j * 512;
                int r = idx >> 3, seg = idx & 7;
                cpa16(dst + (unsigned)r * 144u + (unsigned)seg * 16u,
                      src + (size_t)r * DDIM + seg * 8);
            }
        }
        CP_COMMIT();
    };

    float acc[2][4][4];
#pragma unroll
    for (int mt = 0; mt < 2; mt++)
#pragma unroll
        for (int nt = 0; nt < 4; nt++)
#pragma unroll
            for (int r = 0; r < 4; r++) acc[mt][nt][r] = 0.0f;

    issue(0); issue(1);

    for (int c = 0; c < 8; c++) {
        if (c == 7) { CP_WAIT(0); } else { CP_WAIT(1); }
        __syncthreads();

        const __nv_bfloat16* sAhi = (const __nv_bfloat16*)(smem + (c & 1) * ZI_STAGE);
        const __nv_bfloat16* sAlo = sAhi + 9216;
        const __nv_bfloat16* sBhi = sAhi + 18432;
        const __nv_bfloat16* sBlo = sAhi + 27648;

#pragma unroll
        for (int ks = 0; ks < 4; ks++) {
            const int kc = ks * 16 + (lane & 3) * 2;
            uint32_t ahi[2][4], alo[2][4];
#pragma unroll
            for (int mt = 0; mt < 2; mt++) {
                int base = (wm * 32 + mt * 16 + (lane >> 2)) * 72 + kc;
                ahi[mt][0] = *(const uint32_t*)(sAhi + base);
                ahi[mt][1] = *(const uint32_t*)(sAhi + base + 8 * 72);
                ahi[mt][2] = *(const uint32_t*)(sAhi + base + 8);
                ahi[mt][3] = *(const uint32_t*)(sAhi + base + 8 * 72 + 8);
                alo[mt][0] = *(const uint32_t*)(sAlo + base);
                alo[mt][1] = *(const uint32_t*)(sAlo + base + 8 * 72);
                alo[mt][2] = *(const uint32_t*)(sAlo + base + 8);
                alo[mt][3] = *(const uint32_t*)(sAlo + base + 8 * 72 + 8);
            }
            uint32_t bhi[4][2], blo[4][2];
#pragma unroll
            for (int nt = 0; nt < 4; nt++) {
                int base = (wn * 32 + nt * 8 + (lane >> 2)) * 72 + kc;
                bhi[nt][0] = *(const uint32_t*)(sBhi + base);
                bhi[nt][1] = *(const uint32_t*)(sBhi + base + 8);
                blo[nt][0] = *(const uint32_t*)(sBlo + base);
                blo[nt][1] = *(const uint32_t*)(sBlo + base + 8);
            }
#pragma unroll
            for (int mt = 0; mt < 2; mt++)
#pragma unroll
                for (int nt = 0; nt < 4; nt++) {
                    MMA16816(acc[mt][nt], ahi[mt], bhi[nt]);
                    MMA16816(acc[mt][nt], ahi[mt], blo[nt]);
                    MMA16816(acc[mt][nt], alo[mt], bhi[nt]);
                }
        }
        if (c < 6) { __syncthreads(); issue(c + 2); }
    }

    __syncthreads();
    float* s_out = (float*)smem;
#pragma unroll
    for (int mt = 0; mt < 2; mt++)
#pragma unroll
        for (int nt = 0; nt < 4; nt++) {
            int hr = wm * 32 + mt * 16 + (lane >> 2);
            int nc = wn * 32 + nt * 8 + (lane & 3) * 2;
            s_out[hr * 132 + nc]           = acc[mt][nt][0];
            s_out[hr * 132 + nc + 1]       = acc[mt][nt][1];
            s_out[(hr + 8) * 132 + nc]     = acc[mt][nt][2];
            s_out[(hr + 8) * 132 + nc + 1] = acc[mt][nt][3];
        }
    __syncthreads();

    for (int i = tid; i < 4 * 128 * 32; i += 512) {
        int tg = i >> 12;
        int h  = (i >> 5) & 127;
        int b  = i & 31;
        float bi = bih[l * HDIM + h0 + h];
        int t = (n0 >> 5) + tg;
        g_A[((size_t)(l * TSTEPS + t) * HDIM + h0 + h) * BSZ + b] =
            s_out[h * 132 + tg * 32 + b] + bi;
    }
}

// ---------------- LN over h for each (l,t,b), in place on g_A ---------------
__global__ __launch_bounds__(256) void k_ln(const float* __restrict__ gih,
                                            const float* __restrict__ beih) {
    const int lt = blockIdx.x;
    const int l  = lt >> 11;
    const size_t base = (size_t)lt * HDIM * BSZ;
    const int tid = threadIdx.x;
    const int b = tid & 31, w = tid >> 5;

    float v[64];
    float s = 0.0f, q = 0.0f;
#pragma unroll
    for (int i = 0; i < 64; i++) {
        float xv = g_A[base + (size_t)(w * 64 + i) * BSZ + b];
        v[i] = xv;
        s += xv;
        q = fmaf(xv, xv, q);
    }
    __shared__ float rs[8][32], rq[8][32], mu_s[32], rstd_s[32];
    rs[w][b] = s; rq[w][b] = q;
    __syncthreads();
    if (w == 0) {
        float ss = 0.0f, qq = 0.0f;
#pragma unroll
        for (int j = 0; j < 8; j++) { ss += rs[j][b]; qq += rq[j][b]; }
        float mu = ss * (1.0f / HDIM);
        float var = qq * (1.0f / HDIM) - mu * mu;
        mu_s[b] = mu;
        rstd_s[b] = rsqrtf(var + EPS);
    }
    __syncthreads();
    float mu = mu_s[b], rstd = rstd_s[b];
#pragma unroll
    for (int i = 0; i < 64; i++) {
        int h = w * 64 + i;
        g_A[base + (size_t)h * BSZ + b] =
            (v[i] - mu) * rstd * gih[l * HDIM + h] + beih[l * HDIM + h];
    }
}

// ---------------- phase 2: HMMA dataflow recurrence -------------------------
// SMEM bytes: Whi 16640 | Wlo 16640 | Hhi 33280 | Hlo 33280 | red 16896 | red2 2048 | stat 768
#define SMEM_RECUR (16640 * 2 + 33280 * 2 + 16896 + 2048 + 768)

__global__ void __launch_bounds__(256, 1)
k_recur(const float* __restrict__ Whh, const float* __restrict__ bhh,
        const float* __restrict__ ghh, const float* __restrict__ behh) {
    extern __shared__ char smc[];
    __nv_bfloat16* Whi_s = (__nv_bfloat16*)smc;            // [16][520]
    __nv_bfloat16* Wlo_s = Whi_s + 16 * 520;
    __nv_bfloat16* Hhi_s = Wlo_s + 16 * 520;               // [32 b][520 k]
    __nv_bfloat16* Hlo_s = Hhi_s + 32 * 520;
    float* red  = (float*)(Hlo_s + 32 * 520);              // [8 w][16 r][33]
    float* red2 = red + 8 * 16 * 33;                       // [8 w][2][32]
    float* stat = red2 + 512;

    const int cta = blockIdx.x;
    const int l   = cta >> 5;
    const int cl  = cta & 31;
    const int r0  = cl * 16;
    const int tid = threadIdx.x;
    const int w   = tid >> 5;
    const int lane = tid & 31;
    const int b   = lane;

    // ---- stationary W rows: fp32 -> split bf16 in smem [r][k] ----
    const float* Wl = Whh + (size_t)l * HDIM * HDIM + (size_t)r0 * HDIM;
    for (int idx = tid; idx < 16 * 512; idx += 256) {
        int r = idx >> 9, k = idx & 511;
        float v = Wl[r * 512 + k];
        __nv_bfloat16 hi = __float2bfloat16(v);
        Whi_s[r * 520 + k] = hi;
        Wlo_s[r * 520 + k] = __float2bfloat16(v - __bfloat162float(hi));
    }

    // thread (w,b) owns rows r0+2w, r0+2w+1
    const float bhA = bhh[l * HDIM + r0 + 2 * w],  bhB = bhh[l * HDIM + r0 + 2 * w + 1];
    const float ghA = ghh[l * HDIM + r0 + 2 * w],  ghB = ghh[l * HDIM + r0 + 2 * w + 1];
    const float beA = behh[l * HDIM + r0 + 2 * w], beB = behh[l * HDIM + r0 + 2 * w + 1];

    const unsigned* hline = g_hflag + l * 32;
    const unsigned* pline = g_pflag + l * 32;
    unsigned* my_hflag = g_hflag + l * 32 + cl;
    unsigned* my_pflag = g_pflag + l * 32 + cl;

    const unsigned Hhi_base = (unsigned)__cvta_generic_to_shared(Hhi_s);
    const unsigned Hlo_base = (unsigned)__cvta_generic_to_shared(Hlo_s);

    __syncthreads();

    for (int s = 0; s < TSTEPS; s++) {
        const __nv_bfloat16* hin_hi = g_hhi + (size_t)((s & 1) * LNUM + l) * (BSZ * HDIM);
        const __nv_bfloat16* hin_lo = g_hlo + (size_t)((s & 1) * LNUM + l) * (BSZ * HDIM);
        unsigned* hout_hi = (unsigned*)(g_hhi + (size_t)(((s + 1) & 1) * LNUM + l) * (BSZ * HDIM));
        unsigned* hout_lo = (unsigned*)(g_hlo + (size_t)(((s + 1) & 1) * LNUM + l) * (BSZ * HDIM));
        float* pb = g_part + (size_t)((s & 1) * LNUM + l) * (32 * 2 * BSZ);

        const float* aptr = g_A + ((size_t)l * TSTEPS + s) * HDIM * BSZ;
        float aA = __ldcs(aptr + (size_t)(r0 + 2 * w) * BSZ + b);
        float aB = __ldcs(aptr + (size_t)(r0 + 2 * w + 1) * BSZ + b);

        // issue one 128-k quarter of both split slabs (32 rows x 256B each)
        auto issue_q = [&](int Q) {
#pragma unroll
            for (int j = 0; j < 4; j++) {
                int t4 = j * 256 + tid;              // 0..1023
                int slab = t4 >> 9;                  // 0: hi, 1: lo
                int row = (t4 >> 4) & 31;
                int cch = t4 & 15;
                unsigned dst = (slab ? Hlo_base : Hhi_base)
                             + (unsigned)row * 1040u + (unsigned)Q * 256u + (unsigned)cch * 16u;
                const __nv_bfloat16* src = (slab ? hin_lo : hin_hi)
                                         + (size_t)row * 512 + Q * 128 + cch * 8;
                cpa16(dst, src);
            }
            CP_COMMIT();
        };

        float acc[4][4];
#pragma unroll
        for (int nf = 0; nf < 4; nf++)
#pragma unroll
            for (int r = 0; r < 4; r++) acc[nf][r] = 0.0f;

        // HMMA over this warp's 16-k slice of quarter Q
        auto mv = [&](int Q) {
            const int kc = Q * 128 + w * 16 + (lane & 3) * 2;
            const int r_l = lane >> 2;
            int abase = r_l * 520 + kc;
            uint32_t Ahi[4], Alo[4];
            Ahi[0] = *(const uint32_t*)(Whi_s + abase);
            Ahi[1] = *(const uint32_t*)(Whi_s + abase + 8 * 520);
            Ahi[2] = *(const uint32_t*)(Whi_s + abase + 8);
            Ahi[3] = *(const uint32_t*)(Whi_s + abase + 8 * 520 + 8);
            Alo[0] = *(const uint32_t*)(Wlo_s + abase);
            Alo[1] = *(const uint32_t*)(Wlo_s + abase + 8 * 520);
            Alo[2] = *(const uint32_t*)(Wlo_s + abase + 8);
            Alo[3] = *(const uint32_t*)(Wlo_s + abase + 8 * 520 + 8);
#pragma unroll
            for (int nf = 0; nf < 4; nf++) {
                int bbase = (nf * 8 + r_l) * 520 + kc;
                uint32_t Bhi[2], Blo[2];
                Bhi[0] = *(const uint32_t*)(Hhi_s + bbase);
                Bhi[1] = *(const uint32_t*)(Hhi_s + bbase + 8);
                Blo[0] = *(const uint32_t*)(Hlo_s + bbase);
                Blo[1] = *(const uint32_t*)(Hlo_s + bbase + 8);
                MMA16816(acc[nf], Ahi, Bhi);
                MMA16816(acc[nf], Ahi, Blo);
                MMA16816(acc[nf], Alo, Bhi);
            }
        };

        if (w == 0) poll8(hline, 0, (unsigned)s);
        __syncthreads();
        issue_q(0);
        if (w == 0) poll8(hline, 1, (unsigned)s);
        __syncthreads();
        issue_q(1);

        CP_WAIT(1); __syncthreads();
        mv(0);
        if (w == 0) poll8(hline, 2, (unsigned)s);
        __syncthreads();
        issue_q(2);

        CP_WAIT(1); __syncthreads();
        mv(1);
        if (w == 0) poll8(hline, 3, (unsigned)s);
        __syncthreads();
        issue_q(3);

        CP_WAIT(1); __syncthreads();
        mv(2);
        CP_WAIT(0); __syncthreads();
        mv(3);

        // ---- store warp partial accs to red[w][r][b] ----
        {
            const int rr = lane >> 2;
            const int bc = (lane & 3) * 2;
#pragma unroll
            for (int nf = 0; nf < 4; nf++) {
                int bb = nf * 8 + bc;
                red[(w * 16 + rr) * 33 + bb]         = acc[nf][0];
                red[(w * 16 + rr) * 33 + bb + 1]     = acc[nf][1];
                red[(w * 16 + rr + 8) * 33 + bb]     = acc[nf][2];
                red[(w * 16 + rr + 8) * 33 + bb + 1] = acc[nf][3];
            }
        }
        __syncthreads();

        // ---- z for own 2 rows (sum 8 warp k-slices) ----
        float zA = bhA, zB = bhB;
#pragma unroll
        for (int wp = 0; wp < 8; wp++) {
            zA += red[(wp * 16 + 2 * w) * 33 + b];
            zB += red[(wp * 16 + 2 * w + 1) * 33 + b];
        }
        red2[(w * 2 + 0) * 32 + b] = zA + zB;
        red2[(w * 2 + 1) * 32 + b] = fmaf(zA, zA, zB * zB);
        __syncthreads();

        // ---- warp 0 publishes CTA partials; warps 0-1 gather global stats ----
        if (w == 0) {
            float S = 0.f, Q = 0.f;
#pragma unroll
            for (int j = 0; j < 8; j++) { S += red2[(j * 2) * 32 + b]; Q += red2[(j * 2 + 1) * 32 + b]; }
            pb[cl * 64 + b]      = S;
            pb[cl * 64 + 32 + b] = Q;
            __syncwarp();
            if (b == 0) red_release_add1(my_pflag);
            poll32(pline, (unsigned)(s + 1));
            float S2 = 0.f, Q2 = 0.f;
#pragma unroll 4
            for (int cc = 0; cc < 16; cc++) {
                S2 += __ldcg(pb + cc * 64 + b);
                Q2 += __ldcg(pb + cc * 64 + 32 + b);
            }
            stat[64 + b] = S2; stat[96 + b] = Q2;
        } else if (w == 1) {
            poll32(pline, (unsigned)(s + 1));
            float S2 = 0.f, Q2 = 0.f;
#pragma unroll 4
            for (int cc = 16; cc < 32; cc++) {
                S2 += __ldcg(pb + cc * 64 + b);
                Q2 += __ldcg(pb + cc * 64 + 32 + b);
            }
            stat[128 + b] = S2; stat[160 + b] = Q2;
        }
        if (w < 2) {
            asm volatile("bar.sync 1, 64;" ::: "memory");
            if (w == 0) {
                float S = stat[64 + b] + stat[128 + b];
                float Q = stat[96 + b] + stat[160 + b];
                float mu = S * (1.0f / HDIM);
                float var = Q * (1.0f / HDIM) - mu * mu;
                stat[b] = mu;
                stat[32 + b] = rsqrtf(var + EPS);
            }
        }
        __syncthreads();

        // ---- h^{s+1} for own rows: tanh, split, packed u32 publish ----
        float mu = stat[b], rstd = stat[32 + b];
        float hA = tanhf(aA + (zA - mu) * rstd * ghA + beA);
        float hB = tanhf(aB + (zB - mu) * rstd * ghB + beB);
        __nv_bfloat16 hAhi = __float2bfloat16(hA);
        __nv_bfloat16 hBhi = __float2bfloat16(hB);
        __nv_bfloat16 hAlo = __float2bfloat16(hA - __bfloat162float(hAhi));
        __nv_bfloat16 hBlo = __float2bfloat16(hB - __bfloat162float(hBhi));
        unsigned hipack = (unsigned)bfbits(hAhi) | ((unsigned)bfbits(hBhi) << 16);
        unsigned lopack = (unsigned)bfbits(hAlo) | ((unsigned)bfbits(hBlo) << 16);
        int u32idx = b * 256 + cl * 8 + w;          // [b][k-pair]
        hout_hi[u32idx] = hipack;
        hout_lo[u32idx] = lopack;
        if (l == 3) {
            int h3idx = (s * 32 + b) * 256 + cl * 8 + w;
            ((unsigned*)g_H3hi)[h3idx] = hipack;
            ((unsigned*)g_H3lo)[h3idx] = lopack;
        }
        if (s == TSTEPS - 1) {
            g_h[(size_t)l * (HDIM * BSZ) + (size_t)(r0 + 2 * w) * BSZ + b]     = hA;
            g_h[(size_t)l * (HDIM * BSZ) + (size_t)(r0 + 2 * w + 1) * BSZ + b] = hB;
        }
        __syncthreads();
        if (tid == 0) red_release_add1(my_hflag);
    }
}

// ---------------- phase 3 (HMMA): out = h3 @ W_ho^T + b_ho + x --------------
__global__ __launch_bounds__(512) void k_gemm_out_mma(const float* __restrict__ bho,
                                                      const float* __restrict__ x,
                                                      float* __restrict__ out) {
    extern __shared__ char smem[];
    const unsigned sb = (unsigned)__cvta_generic_to_shared(smem);
    const int tid = threadIdx.x;
    const int lane = tid & 31;
    const int w = tid >> 5;
    const int wm = w >> 2, wn = w & 3;
    const int d0 = blockIdx.x * 128;
    const int n0 = blockIdx.y * 128;

    const __nv_bfloat16* gAhi = g_WOhi + (size_t)d0 * HDIM;
    const __nv_bfloat16* gAlo = g_WOlo + (size_t)d0 * HDIM;
    const __nv_bfloat16* gBhi = g_H3hi + (size_t)n0 * HDIM;
    const __nv_bfloat16* gBlo = g_H3lo + (size_t)n0 * HDIM;

    auto issue = [&](int c) {
        const unsigned stg = sb + (unsigned)(c & 1) * ZI_STAGE;
        const __nv_bfloat16* srcs[4] = {gAhi, gAlo, gBhi, gBlo};
#pragma unroll
        for (int op = 0; op < 4; op++) {
            const __nv_bfloat16* src = srcs[op] + c * 64;
            unsigned dst = stg + (unsigned)op * 18432u;
#pragma unroll
            for (int j = 0; j < 2; j++) {
                int idx = tid + j * 512;
                int r = idx >> 3, seg = idx & 7;
                cpa16(dst + (unsigned)r * 144u + (unsigned)seg * 16u,
                      src + (size_t)r * HDIM + seg * 8);
            }
        }
        CP_COMMIT();
    };

    float acc[2][4][4];
#pragma unroll
    for (int mt = 0; mt < 2; mt++)
#pragma unroll
        for (int nt = 0; nt < 4; nt++)
#pragma unroll
            for (int r = 0; r < 4; r++) acc[mt][nt][r] = 0.0f;

    issue(0); issue(1);

    for (int c = 0; c < 8; c++) {
        if (c == 7) { CP_WAIT(0); } else { CP_WAIT(1); }
        __syncthreads();

        const __nv_bfloat16* sAhi = (const __nv_bfloat16*)(smem + (c & 1) * ZI_STAGE);
        const __nv_bfloat16* sAlo = sAhi + 9216;
        const __nv_bfloat16* sBhi = sAhi + 18432;
        const __nv_bfloat16* sBlo = sAhi + 27648;

#pragma unroll
        for (int ks = 0; ks < 4; ks++) {
            const int kc = ks * 16 + (lane & 3) * 2;
            uint32_t ahi[2][4], alo[2][4];
#pragma unroll
            for (int mt = 0; mt < 2; mt++) {
                int base = (wm * 32 + mt * 16 + (lane >> 2)) * 72 + kc;
                ahi[mt][0] = *(const uint32_t*)(sAhi + base);
                ahi[mt][1] = *(const uint32_t*)(sAhi + base + 8 * 72);
                ahi[mt][2] = *(const uint32_t*)(sAhi + base + 8);
                ahi[mt][3] = *(const uint32_t*)(sAhi + base + 8 * 72 + 8);
                alo[mt][0] = *(const uint32_t*)(sAlo + base);
                alo[mt][1] = *(const uint32_t*)(sAlo + base + 8 * 72);
                alo[mt][2] = *(const uint32_t*)(sAlo + base + 8);
                alo[mt][3] = *(const uint32_t*)(sAlo + base + 8 * 72 + 8);
            }
            uint32_t bhi[4][2], blo[4][2];
#pragma unroll
            for (int nt = 0; nt < 4; nt++) {
                int base = (wn * 32 + nt * 8 + (lane >> 2)) * 72 + kc;
                bhi[nt][0] = *(const uint32_t*)(sBhi + base);
                bhi[nt][1] = *(const uint32_t*)(sBhi + base + 8);
                blo[nt][0] = *(const uint32_t*)(sBlo + base);
                blo[nt][1] = *(const uint32_t*)(sBlo + base + 8);
            }
#pragma unroll
            for (int mt = 0; mt < 2; mt++)
#pragma unroll
                for (int nt = 0; nt < 4; nt++) {
                    MMA16816(acc[mt][nt], ahi[mt], bhi[nt]);
                    MMA16816(acc[mt][nt], ahi[mt], blo[nt]);
                    MMA16816(acc[mt][nt], alo[mt], bhi[nt]);
                }
        }
        if (c < 6) { __syncthreads(); issue(c + 2); }
    }

    // epilogue: stage as s_out[n][132] so global stores are d-contiguous
    __syncthreads();
    float* s_out = (float*)smem;
#pragma unroll
    for (int mt = 0; mt < 2; mt++)
#pragma unroll
        for (int nt = 0; nt < 4; nt++) {
            int hr = wm * 32 + mt * 16 + (lane >> 2);
            int nc = wn * 32 + nt * 8 + (lane & 3) * 2;
            s_out[nc * 132 + hr]           = acc[mt][nt][0];
            s_out[(nc + 1) * 132 + hr]     = acc[mt][nt][1];
            s_out[nc * 132 + hr + 8]       = acc[mt][nt][2];
            s_out[(nc + 1) * 132 + hr + 8] = acc[mt][nt][3];
        }
    __syncthreads();

    for (int i = tid; i < 128 * 128; i += 512) {
        int n = i >> 7;          // 0..127
        int dd = i & 127;
        int tg = n >> 5, bb = n & 31;
        int t = (n0 >> 5) + tg;
        int d = d0 + dd;
        size_t oidx = ((size_t)bb * TSTEPS + t) * DDIM + d;
        out[oidx] = s_out[n * 132 + dd] + bho[d] + x[oidx];
    }
}

// ---------------- h_final: [L,B,H] from g_h ([l][h][b]) ---------------------
__global__ void k_hfinal(float* __restrict__ out2) {
    int idx = blockIdx.x * 256 + threadIdx.x;
    int l = idx >> 14;
    int rem = idx & 16383;
    int bb = rem >> 9;
    int hh = rem & 511;
    out2[idx] = g_h[(size_t)l * (HDIM * BSZ) + (size_t)hh * BSZ + bb];
}

// ---------------- launch -----------------------------------------------------
extern "C" void kernel_launch(void* const* d_in, const int* in_sizes, int n_in,
                              void* d_out, int out_size) {
    const float* x    = (const float*)d_in[0];
    const float* Wih  = (const float*)d_in[1];
    const float* bih  = (const float*)d_in[2];
    const float* gih  = (const float*)d_in[3];
    const float* beih = (const float*)d_in[4];
    const float* Whh  = (const float*)d_in[5];
    const float* bhh  = (const float*)d_in[6];
    const float* ghh  = (const float*)d_in[7];
    const float* behh = (const float*)d_in[8];
    const float* Who  = (const float*)d_in[9];
    const float* bho  = (const float*)d_in[10];
    float* out = (float*)d_out;

    cudaFuncSetAttribute(k_recur, cudaFuncAttributeMaxDynamicSharedMemorySize, SMEM_RECUR);
    cudaFuncSetAttribute(k_gemm_zi_mma, cudaFuncAttributeMaxDynamicSharedMemorySize, ZI_SMEM);
    cudaFuncSetAttribute(k_gemm_out_mma, cudaFuncAttributeMaxDynamicSharedMemorySize, ZI_SMEM);

    k_init<<<64, 256>>>();
    {   // W_ih split
        __nv_bfloat16 *dhi, *dlo;
        cudaGetSymbolAddress((void**)&dhi, g_Whi);
        cudaGetSymbolAddress((void**)&dlo, g_Wlo);
        int n4 = LNUM * HDIM * DDIM / 4;
        k_cvt_split<<<(n4 + 255) / 256, 256>>>(Wih, dhi, dlo, n4);
    }
    {   // W_ho split
        __nv_bfloat16 *dhi, *dlo;
        cudaGetSymbolAddress((void**)&dhi, g_WOhi);
        cudaGetSymbolAddress((void**)&dlo, g_WOlo);
        int n4 = DDIM * HDIM / 4;
        k_cvt_split<<<(n4 + 255) / 256, 256>>>(Who, dhi, dlo, n4);
    }
    k_cvt_x<<<(TSTEPS * BSZ * DDIM / 4 + 255) / 256, 256>>>(x);
    k_gemm_zi_mma<<<dim3(16, 512), 512, ZI_SMEM>>>(bih);
    k_ln<<<LNUM * TSTEPS, 256>>>(gih, beih);
    k_recur<<<NCTA, 256, SMEM_RECUR>>>(Whh, bhh, ghh, behh);
    k_gemm_out_mma<<<dim3(4, 512), 512, ZI_SMEM>>>(bho, x, out);
    k_hfinal<<<256, 256>>>(out + (size_t)BSZ * TSTEPS * DDIM);
}